// round 1
// baseline (speedup 1.0000x reference)
#include <cuda_runtime.h>
#include <cuda_bf16.h>
#include <cstdint>

// Problem constants
#define BB 2
#define SS 2048
#define DD 1024
#define HH 16
#define HEADD 64
#define MROWS (BB*SS)              // 4096
#define OUT_ELEMS ((size_t)BB*SS*DD)   // 4,194,304

// Scratch (device globals; no allocation allowed)
__device__ float g_Q[(size_t)BB*HH*SS*HEADD];
__device__ float g_K[(size_t)BB*HH*SS*HEADD];
__device__ float g_V[(size_t)BB*HH*SS*HEADD];
__device__ float g_Ob[(size_t)BB*SS*DD];
__device__ float g_L[(size_t)BB*HH*SS];

// ---------------------------------------------------------------------------
// GEMM: Y = X @ W^T + bias.  X [4096,1024] row-major, W [1024,1024] row-major.
// BM=128, BN=128, BK=16, 256 threads, 8x8 per-thread microtile.
// mode 0/1/2: write to g_Q/g_K/g_V with [B,H,S,HEAD] remap.
// mode 3:     X = g_Ob, plain row-major write to Yout.
// ---------------------------------------------------------------------------
__global__ void gemm_bias_kernel(const float* __restrict__ Xin,
                                 const float* __restrict__ W,
                                 const float* __restrict__ bias,
                                 float* __restrict__ Yout,
                                 int mode)
{
    __shared__ float As[16 * 128];
    __shared__ float Bs[16 * 128];

    const float* X = (mode == 3) ? g_Ob : Xin;
    float* Yq = (mode == 0) ? g_Q : (mode == 1) ? g_K : g_V;

    const int tid = threadIdx.x;
    const int tx = tid & 15;        // 0..15 (N)
    const int ty = tid >> 4;        // 0..15 (M)
    const int m0 = blockIdx.y * 128;
    const int n0 = blockIdx.x * 128;

    float c[8][8];
#pragma unroll
    for (int i = 0; i < 8; i++)
#pragma unroll
        for (int j = 0; j < 8; j++) c[i][j] = 0.f;

    for (int k0 = 0; k0 < 1024; k0 += 16) {
#pragma unroll
        for (int t = 0; t < 2; t++) {
            int f4 = tid + t * 256;         // 0..511
            int row = f4 >> 2;              // 0..127
            int kq = (f4 & 3) << 2;         // 0,4,8,12
            float4 a = *(const float4*)&X[(size_t)(m0 + row) * 1024 + k0 + kq];
            As[(kq + 0) * 128 + row] = a.x;
            As[(kq + 1) * 128 + row] = a.y;
            As[(kq + 2) * 128 + row] = a.z;
            As[(kq + 3) * 128 + row] = a.w;
            float4 b = *(const float4*)&W[(size_t)(n0 + row) * 1024 + k0 + kq];
            Bs[(kq + 0) * 128 + row] = b.x;
            Bs[(kq + 1) * 128 + row] = b.y;
            Bs[(kq + 2) * 128 + row] = b.z;
            Bs[(kq + 3) * 128 + row] = b.w;
        }
        __syncthreads();

#pragma unroll
        for (int kk = 0; kk < 16; kk++) {
            float a[8], b[8];
            *(float4*)&a[0] = *(float4*)&As[kk * 128 + ty * 8];
            *(float4*)&a[4] = *(float4*)&As[kk * 128 + ty * 8 + 4];
            *(float4*)&b[0] = *(float4*)&Bs[kk * 128 + tx * 8];
            *(float4*)&b[4] = *(float4*)&Bs[kk * 128 + tx * 8 + 4];
#pragma unroll
            for (int i = 0; i < 8; i++)
#pragma unroll
                for (int j = 0; j < 8; j++) c[i][j] += a[i] * b[j];
        }
        __syncthreads();
    }

    // Epilogue
#pragma unroll
    for (int i = 0; i < 8; i++) {
        int m = m0 + ty * 8 + i;
#pragma unroll
        for (int j4 = 0; j4 < 8; j4 += 4) {
            int n = n0 + tx * 8 + j4;
            float4 v;
            v.x = c[i][j4 + 0] + bias[n + 0];
            v.y = c[i][j4 + 1] + bias[n + 1];
            v.z = c[i][j4 + 2] + bias[n + 2];
            v.w = c[i][j4 + 3] + bias[n + 3];
            if (mode == 3) {
                *(float4*)&Yout[(size_t)m * 1024 + n] = v;
            } else {
                int b = m >> 11;       // batch
                int s = m & 2047;
                int h = n >> 6;        // head
                int hd = n & 63;
                *(float4*)&Yq[((((size_t)b * HH + h) * SS) + s) * HEADD + hd] = v;
            }
        }
    }
}

// ---------------------------------------------------------------------------
// Attention: per (b,h,q-tile of 64 rows).
// Single pass over causal k-tiles: S = QK^T/8, p = exp(S) (unnormalized),
// write p to attn_weights, accumulate rowsum L and O_unnorm = p @ V.
// Zero-fill strictly-upper tiles. Normalize O in regs; store L for rescale.
// ---------------------------------------------------------------------------
__global__ void attn_kernel(float* __restrict__ d_attn)
{
    __shared__ float Qs[64 * 64];
    __shared__ float KVs[64 * 64];
    __shared__ float Ps[64 * 64];

    const int bh = blockIdx.y;                       // 0..31
    const int qt = (gridDim.x - 1) - blockIdx.x;     // reversed: big tiles first
    const int tid = threadIdx.x;
    const int tx = tid & 15;
    const int ty = tid >> 4;

    const float* Qg = g_Q + ((size_t)bh * SS + qt * 64) * HEADD;
#pragma unroll
    for (int t = 0; t < 4; t++) {
        int f4 = tid + t * 256;
        int row = f4 >> 4;
        int c4 = (f4 & 15) << 2;
        *(float4*)&Qs[row * 64 + c4] = *(const float4*)&Qg[row * 64 + c4];
    }

    float o[4][4];
    float lsum[4] = {0.f, 0.f, 0.f, 0.f};
#pragma unroll
    for (int i = 0; i < 4; i++)
#pragma unroll
        for (int j = 0; j < 4; j++) o[i][j] = 0.f;

    for (int kt = 0; kt <= qt; kt++) {
        __syncthreads();   // Qs visible (1st iter) / prior Vs reads done

        const float* Kg = g_K + ((size_t)bh * SS + kt * 64) * HEADD;
#pragma unroll
        for (int t = 0; t < 4; t++) {
            int f4 = tid + t * 256;
            int key = f4 >> 4;
            int hd = (f4 & 15) << 2;
            float4 v = *(const float4*)&Kg[key * 64 + hd];
            KVs[(hd + 0) * 64 + key] = v.x;   // transposed: [hd][key]
            KVs[(hd + 1) * 64 + key] = v.y;
            KVs[(hd + 2) * 64 + key] = v.z;
            KVs[(hd + 3) * 64 + key] = v.w;
        }
        __syncthreads();

        float s[4][4];
#pragma unroll
        for (int i = 0; i < 4; i++)
#pragma unroll
            for (int j = 0; j < 4; j++) s[i][j] = 0.f;

#pragma unroll
        for (int kk = 0; kk < 64; kk++) {
            float4 bb = *(float4*)&KVs[kk * 64 + tx * 4];
            float a0 = Qs[(ty * 4 + 0) * 64 + kk];
            float a1 = Qs[(ty * 4 + 1) * 64 + kk];
            float a2 = Qs[(ty * 4 + 2) * 64 + kk];
            float a3 = Qs[(ty * 4 + 3) * 64 + kk];
            s[0][0] += a0 * bb.x; s[0][1] += a0 * bb.y; s[0][2] += a0 * bb.z; s[0][3] += a0 * bb.w;
            s[1][0] += a1 * bb.x; s[1][1] += a1 * bb.y; s[1][2] += a1 * bb.z; s[1][3] += a1 * bb.w;
            s[2][0] += a2 * bb.x; s[2][1] += a2 * bb.y; s[2][2] += a2 * bb.z; s[2][3] += a2 * bb.w;
            s[3][0] += a3 * bb.x; s[3][1] += a3 * bb.y; s[3][2] += a3 * bb.z; s[3][3] += a3 * bb.w;
        }

        const int gqBase = qt * 64 + ty * 4;
        const int gkBase = kt * 64 + tx * 4;
#pragma unroll
        for (int i = 0; i < 4; i++) {
            int gq = gqBase + i;
            float4 pv;
            float p0 = (gkBase + 0 <= gq) ? __expf(s[i][0] * 0.125f) : 0.f;
            float p1 = (gkBase + 1 <= gq) ? __expf(s[i][1] * 0.125f) : 0.f;
            float p2 = (gkBase + 2 <= gq) ? __expf(s[i][2] * 0.125f) : 0.f;
            float p3 = (gkBase + 3 <= gq) ? __expf(s[i][3] * 0.125f) : 0.f;
            pv.x = p0; pv.y = p1; pv.z = p2; pv.w = p3;
            lsum[i] += p0 + p1 + p2 + p3;
            Ps[(ty * 4 + i) * 64 + tx * 4 + 0] = p0;
            Ps[(ty * 4 + i) * 64 + tx * 4 + 1] = p1;
            Ps[(ty * 4 + i) * 64 + tx * 4 + 2] = p2;
            Ps[(ty * 4 + i) * 64 + tx * 4 + 3] = p3;
            *(float4*)&d_attn[((size_t)bh * SS + gq) * SS + gkBase] = pv;
        }
        __syncthreads();  // Ps written; KVs (K) reads done

        const float* Vg = g_V + ((size_t)bh * SS + kt * 64) * HEADD;
#pragma unroll
        for (int t = 0; t < 4; t++) {
            int f4 = tid + t * 256;
            int key = f4 >> 4;
            int hd = (f4 & 15) << 2;
            *(float4*)&KVs[key * 64 + hd] = *(const float4*)&Vg[key * 64 + hd];
        }
        __syncthreads();

#pragma unroll
        for (int kk = 0; kk < 64; kk++) {
            float4 bb = *(float4*)&KVs[kk * 64 + tx * 4];
            float a0 = Ps[(ty * 4 + 0) * 64 + kk];
            float a1 = Ps[(ty * 4 + 1) * 64 + kk];
            float a2 = Ps[(ty * 4 + 2) * 64 + kk];
            float a3 = Ps[(ty * 4 + 3) * 64 + kk];
            o[0][0] += a0 * bb.x; o[0][1] += a0 * bb.y; o[0][2] += a0 * bb.z; o[0][3] += a0 * bb.w;
            o[1][0] += a1 * bb.x; o[1][1] += a1 * bb.y; o[1][2] += a1 * bb.z; o[1][3] += a1 * bb.w;
            o[2][0] += a2 * bb.x; o[2][1] += a2 * bb.y; o[2][2] += a2 * bb.z; o[2][3] += a2 * bb.w;
            o[3][0] += a3 * bb.x; o[3][1] += a3 * bb.y; o[3][2] += a3 * bb.z; o[3][3] += a3 * bb.w;
        }
    }

    // Zero strictly-upper k-tiles of attn_weights
    {
        float4 z = make_float4(0.f, 0.f, 0.f, 0.f);
        for (int kt = qt + 1; kt < SS / 64; kt++) {
#pragma unroll
            for (int i = 0; i < 4; i++) {
                int gq = qt * 64 + ty * 4 + i;
                *(float4*)&d_attn[((size_t)bh * SS + gq) * SS + kt * 64 + tx * 4] = z;
            }
        }
    }

    // Row-sum reduction across the 16 tx threads
    __syncthreads();   // PV reads of Ps done
#pragma unroll
    for (int i = 0; i < 4; i++) Ps[(ty * 4 + i) * 16 + tx] = lsum[i];
    __syncthreads();

    const int b = bh >> 4;
    const int h = bh & 15;
#pragma unroll
    for (int i = 0; i < 4; i++) {
        float tot = 0.f;
#pragma unroll
        for (int t = 0; t < 16; t++) tot += Ps[(ty * 4 + i) * 16 + t];
        float inv = 1.f / tot;
        int srow = qt * 64 + ty * 4 + i;
        if (tx == 0) g_L[(size_t)bh * SS + srow] = tot;
        float4 v;
        v.x = o[i][0] * inv;
        v.y = o[i][1] * inv;
        v.z = o[i][2] * inv;
        v.w = o[i][3] * inv;
        *(float4*)&g_Ob[((size_t)b * SS + srow) * DD + h * 64 + tx * 4] = v;
    }
}

// ---------------------------------------------------------------------------
// Rescale attn_weights rows by 1/L (only the written lower-triangle tiles)
// ---------------------------------------------------------------------------
__global__ void rescale_kernel(float* __restrict__ d_attn)
{
    size_t row = blockIdx.x;                // 0 .. B*H*S-1
    int q = (int)(row & (SS - 1));
    float inv = 1.f / g_L[row];
    int limit = ((q >> 6) + 1) << 6;        // tiles actually written
    float* p = d_attn + row * SS;
    for (int k = threadIdx.x * 4; k < limit; k += blockDim.x * 4) {
        float4 v = *(float4*)&p[k];
        v.x *= inv; v.y *= inv; v.z *= inv; v.w *= inv;
        *(float4*)&p[k] = v;
    }
}

// ---------------------------------------------------------------------------
extern "C" void kernel_launch(void* const* d_in, const int* in_sizes, int n_in,
                              void* d_out, int out_size)
{
    const float* queries = (const float*)d_in[0];
    const float* keys    = (const float*)d_in[1];
    const float* values  = (const float*)d_in[2];
    // d_in[3] = attn_mask (bool, causal) — structure known, applied analytically
    const float* wq = (const float*)d_in[4];
    const float* bq = (const float*)d_in[5];
    const float* wk = (const float*)d_in[6];
    const float* bk = (const float*)d_in[7];
    const float* wv = (const float*)d_in[8];
    const float* bv = (const float*)d_in[9];
    const float* wo = (const float*)d_in[10];
    const float* bo = (const float*)d_in[11];

    float* out   = (float*)d_out;
    float* attnW = out + OUT_ELEMS;

    dim3 gg(DD / 128, MROWS / 128);   // (8, 32)

    gemm_bias_kernel<<<gg, 256>>>(queries, wq, bq, nullptr, 0);
    gemm_bias_kernel<<<gg, 256>>>(keys,    wk, bk, nullptr, 1);
    gemm_bias_kernel<<<gg, 256>>>(values,  wv, bv, nullptr, 2);

    dim3 ga(SS / 64, BB * HH);        // (32, 32)
    attn_kernel<<<ga, 256>>>(attnW);

    rescale_kernel<<<BB * HH * SS, 256>>>(attnW);

    gemm_bias_kernel<<<gg, 256>>>(nullptr, wo, bo, out, 3);
}

// round 3
// speedup vs baseline: 1.4283x; 1.4283x over previous
#include <cuda_runtime.h>
#include <cuda_bf16.h>
#include <cstdint>

// Problem constants
#define BB 2
#define SS 2048
#define DD 1024
#define HH 16
#define HEADD 64
#define MROWS (BB*SS)                  // 4096
#define OUT_ELEMS ((size_t)BB*SS*DD)   // 4,194,304

// Scratch (device globals; no allocation allowed)
__device__ float g_Q[(size_t)BB*HH*SS*HEADD];
__device__ float g_K[(size_t)BB*HH*SS*HEADD];
__device__ float g_V[(size_t)BB*HH*SS*HEADD];
__device__ float g_Ob[(size_t)BB*SS*DD];
__device__ float g_L[(size_t)BB*HH*SS];
// bf16 hi/lo split buffers (reused across the 4 GEMMs)
__device__ __nv_bfloat16 g_Xh[(size_t)MROWS*DD];
__device__ __nv_bfloat16 g_Xl[(size_t)MROWS*DD];
__device__ __nv_bfloat16 g_Wh[(size_t)DD*DD];
__device__ __nv_bfloat16 g_Wl[(size_t)DD*DD];

// ---------------------------------------------------------------------------
// Warp-level MMA helpers (plain sm_103-safe: mma.sync + ldmatrix, sm_80 ISA)
// ---------------------------------------------------------------------------
__device__ __forceinline__ uint32_t smem_to_u32(const void* p) {
    uint32_t a;
    asm("{ .reg .u64 t; cvta.to.shared.u64 t, %1; cvt.u32.u64 %0, t; }"
        : "=r"(a) : "l"(p));
    return a;
}

__device__ __forceinline__ void ldsm4(uint32_t* r, uint32_t addr) {
    asm volatile("ldmatrix.sync.aligned.m8n8.x4.shared.b16 {%0,%1,%2,%3}, [%4];"
        : "=r"(r[0]), "=r"(r[1]), "=r"(r[2]), "=r"(r[3]) : "r"(addr));
}

__device__ __forceinline__ void mma_bf16(float* c, const uint32_t* a, const uint32_t* b) {
    asm volatile(
        "mma.sync.aligned.m16n8k16.row.col.f32.bf16.bf16.f32 "
        "{%0,%1,%2,%3}, {%4,%5,%6,%7}, {%8,%9}, {%0,%1,%2,%3};"
        : "+f"(c[0]), "+f"(c[1]), "+f"(c[2]), "+f"(c[3])
        : "r"(a[0]), "r"(a[1]), "r"(a[2]), "r"(a[3]), "r"(b[0]), "r"(b[1]));
}

// ---------------------------------------------------------------------------
// fp32 -> bf16 hi/lo split conversion.
// dst_sel 0 -> g_Xh/g_Xl ; 1 -> g_Wh/g_Wl.  src==nullptr -> read g_Ob.
// ---------------------------------------------------------------------------
__global__ void cvt_kernel(const float4* __restrict__ src, int dst_sel, int n4)
{
    int i = blockIdx.x * blockDim.x + threadIdx.x;
    if (i >= n4) return;
    const float4* s = src ? src : (const float4*)g_Ob;
    float4 v = s[i];
    __nv_bfloat16 h0 = __float2bfloat16(v.x);
    __nv_bfloat16 h1 = __float2bfloat16(v.y);
    __nv_bfloat16 h2 = __float2bfloat16(v.z);
    __nv_bfloat16 h3 = __float2bfloat16(v.w);
    __nv_bfloat16 l0 = __float2bfloat16(v.x - __bfloat162float(h0));
    __nv_bfloat16 l1 = __float2bfloat16(v.y - __bfloat162float(h1));
    __nv_bfloat16 l2 = __float2bfloat16(v.z - __bfloat162float(h2));
    __nv_bfloat16 l3 = __float2bfloat16(v.w - __bfloat16_as_ushort(h3) * 0.f - __bfloat162float(h3));
    uint2 H, L;
    H.x = ((uint32_t)__bfloat16_as_ushort(h1) << 16) | __bfloat16_as_ushort(h0);
    H.y = ((uint32_t)__bfloat16_as_ushort(h3) << 16) | __bfloat16_as_ushort(h2);
    L.x = ((uint32_t)__bfloat16_as_ushort(l1) << 16) | __bfloat16_as_ushort(l0);
    L.y = ((uint32_t)__bfloat16_as_ushort(l3) << 16) | __bfloat16_as_ushort(l2);
    ((uint2*)(dst_sel ? g_Wh : g_Xh))[i] = H;
    ((uint2*)(dst_sel ? g_Wl : g_Xl))[i] = L;
}

// ---------------------------------------------------------------------------
// HMMA GEMM: Y[4096,1024] = X @ W^T + bias, 3-pass bf16 split, fp32 acc.
// CTA tile 128x128, K chunk 64. 8 warps = 2(m) x 4(n), each warp 64x32.
// mode 0/1/2: write g_Q/g_K/g_V with [B,H,S,HEAD] remap; mode 3: row-major Yout.
// SMEM: Ah[128][64] | Al | Bh[128][64] | Bl  (bf16, SW128-swizzled 128B rows)
// ---------------------------------------------------------------------------
#define GT_THREADS 256
#define OFF_AL 16384
#define OFF_BH 32768
#define OFF_BL 49152
#define GT_SMEM 65536

__global__ void __launch_bounds__(GT_THREADS, 1)
gemm_tc(const float* __restrict__ bias, float* __restrict__ Yout, int mode)
{
    extern __shared__ char smem[];
    const uint32_t sbase = smem_to_u32(smem);
    const int tid = threadIdx.x;
    const int wid = tid >> 5;
    const int lane = tid & 31;
    const int wm = wid & 1;          // 0..1  (m)
    const int wn = wid >> 1;         // 0..3  (n)
    const int m0 = blockIdx.y * 128;
    const int n0 = blockIdx.x * 128;

    float acc[4][4][4];
#pragma unroll
    for (int i = 0; i < 4; i++)
#pragma unroll
        for (int j = 0; j < 4; j++)
#pragma unroll
            for (int k = 0; k < 4; k++) acc[i][j][k] = 0.f;

    // ldmatrix per-lane addressing components
    const int aRow = wm * 64 + (lane & 15);                       // + mf*16
    const int aSel = lane >> 4;                                   // 16B unit select
    const int aSwz = aRow & 7;
    const int bRow = wn * 32 + (lane & 7) + ((lane >> 4) << 3);   // + p*16
    const int bSel = (lane >> 3) & 1;
    const int bSwz = bRow & 7;

    for (int c = 0; c < 16; c++) {
        const int k0 = c * 64;
        // ---- global -> swizzled smem (hi & lo, A & B) ----
#pragma unroll
        for (int t = 0; t < 4; t++) {
            int i = tid + t * GT_THREADS;   // 0..1023
            int r = i >> 3, u = i & 7;
            int sw = r * 128 + ((u ^ (r & 7)) << 4);
            size_t gx = (size_t)(m0 + r) * DD + k0 + u * 8;
            size_t gw = (size_t)(n0 + r) * DD + k0 + u * 8;
            *(uint4*)(smem + sw)          = *(const uint4*)(g_Xh + gx);
            *(uint4*)(smem + OFF_AL + sw) = *(const uint4*)(g_Xl + gx);
            *(uint4*)(smem + OFF_BH + sw) = *(const uint4*)(g_Wh + gw);
            *(uint4*)(smem + OFF_BL + sw) = *(const uint4*)(g_Wl + gw);
        }
        __syncthreads();

#pragma unroll
        for (int ks = 0; ks < 4; ks++) {
            uint32_t ah[4][4], al[4][4], bh[2][4], bl[2][4];
#pragma unroll
            for (int mf = 0; mf < 4; mf++) {
                uint32_t addr = sbase + (uint32_t)(aRow + mf * 16) * 128
                              + (uint32_t)(((ks * 2 + aSel) ^ aSwz) << 4);
                ldsm4(ah[mf], addr);
                ldsm4(al[mf], addr + OFF_AL);
            }
#pragma unroll
            for (int p = 0; p < 2; p++) {
                uint32_t addr = sbase + OFF_BH + (uint32_t)(bRow + p * 16) * 128
                              + (uint32_t)(((ks * 2 + bSel) ^ bSwz) << 4);
                ldsm4(bh[p], addr);
                ldsm4(bl[p], addr + (OFF_BL - OFF_BH));
            }
#pragma unroll
            for (int mf = 0; mf < 4; mf++) {
#pragma unroll
                for (int nf = 0; nf < 4; nf++) {
                    const int p = nf >> 1, q = (nf & 1) * 2;
                    mma_bf16(acc[mf][nf], ah[mf], &bh[p][q]);   // Xh*Wh
                    mma_bf16(acc[mf][nf], ah[mf], &bl[p][q]);   // Xh*Wl
                    mma_bf16(acc[mf][nf], al[mf], &bh[p][q]);   // Xl*Wh
                }
            }
        }
        __syncthreads();
    }

    // ---- epilogue: bias add + store ----
    float* dstq = (mode == 0) ? g_Q : (mode == 1) ? g_K : g_V;
#pragma unroll
    for (int nf = 0; nf < 4; nf++) {
        const int n = n0 + wn * 32 + nf * 8 + (lane & 3) * 2;
        const float bv0 = bias[n], bv1 = bias[n + 1];
        const int h = n >> 6, hd = n & 63;
#pragma unroll
        for (int mf = 0; mf < 4; mf++) {
            const int m = m0 + wm * 64 + mf * 16 + (lane >> 2);
            float2 v0, v1;
            v0.x = acc[mf][nf][0] + bv0; v0.y = acc[mf][nf][1] + bv1;
            v1.x = acc[mf][nf][2] + bv0; v1.y = acc[mf][nf][3] + bv1;
            if (mode == 3) {
                *(float2*)&Yout[(size_t)m * DD + n] = v0;
                *(float2*)&Yout[(size_t)(m + 8) * DD + n] = v1;
            } else {
                const int b = m >> 11, s = m & 2047;
                *(float2*)&dstq[(((size_t)b * HH + h) * SS + s) * HEADD + hd] = v0;
                *(float2*)&dstq[(((size_t)b * HH + h) * SS + s + 8) * HEADD + hd] = v1;
            }
        }
    }
}

// ---------------------------------------------------------------------------
// Attention (unchanged from R1): per (b,h,q-tile of 64 rows).
// ---------------------------------------------------------------------------
__global__ void attn_kernel(float* __restrict__ d_attn)
{
    __shared__ float Qs[64 * 64];
    __shared__ float KVs[64 * 64];
    __shared__ float Ps[64 * 64];

    const int bh = blockIdx.y;
    const int qt = (gridDim.x - 1) - blockIdx.x;
    const int tid = threadIdx.x;
    const int tx = tid & 15;
    const int ty = tid >> 4;

    const float* Qg = g_Q + ((size_t)bh * SS + qt * 64) * HEADD;
#pragma unroll
    for (int t = 0; t < 4; t++) {
        int f4 = tid + t * 256;
        int row = f4 >> 4;
        int c4 = (f4 & 15) << 2;
        *(float4*)&Qs[row * 64 + c4] = *(const float4*)&Qg[row * 64 + c4];
    }

    float o[4][4];
    float lsum[4] = {0.f, 0.f, 0.f, 0.f};
#pragma unroll
    for (int i = 0; i < 4; i++)
#pragma unroll
        for (int j = 0; j < 4; j++) o[i][j] = 0.f;

    for (int kt = 0; kt <= qt; kt++) {
        __syncthreads();

        const float* Kg = g_K + ((size_t)bh * SS + kt * 64) * HEADD;
#pragma unroll
        for (int t = 0; t < 4; t++) {
            int f4 = tid + t * 256;
            int key = f4 >> 4;
            int hd = (f4 & 15) << 2;
            float4 v = *(const float4*)&Kg[key * 64 + hd];
            KVs[(hd + 0) * 64 + key] = v.x;
            KVs[(hd + 1) * 64 + key] = v.y;
            KVs[(hd + 2) * 64 + key] = v.z;
            KVs[(hd + 3) * 64 + key] = v.w;
        }
        __syncthreads();

        float s[4][4];
#pragma unroll
        for (int i = 0; i < 4; i++)
#pragma unroll
            for (int j = 0; j < 4; j++) s[i][j] = 0.f;

#pragma unroll
        for (int kk = 0; kk < 64; kk++) {
            float4 bb = *(float4*)&KVs[kk * 64 + tx * 4];
            float a0 = Qs[(ty * 4 + 0) * 64 + kk];
            float a1 = Qs[(ty * 4 + 1) * 64 + kk];
            float a2 = Qs[(ty * 4 + 2) * 64 + kk];
            float a3 = Qs[(ty * 4 + 3) * 64 + kk];
            s[0][0] += a0 * bb.x; s[0][1] += a0 * bb.y; s[0][2] += a0 * bb.z; s[0][3] += a0 * bb.w;
            s[1][0] += a1 * bb.x; s[1][1] += a1 * bb.y; s[1][2] += a1 * bb.z; s[1][3] += a1 * bb.w;
            s[2][0] += a2 * bb.x; s[2][1] += a2 * bb.y; s[2][2] += a2 * bb.z; s[2][3] += a2 * bb.w;
            s[3][0] += a3 * bb.x; s[3][1] += a3 * bb.y; s[3][2] += a3 * bb.z; s[3][3] += a3 * bb.w;
        }

        const int gqBase = qt * 64 + ty * 4;
        const int gkBase = kt * 64 + tx * 4;
#pragma unroll
        for (int i = 0; i < 4; i++) {
            int gq = gqBase + i;
            float4 pv;
            float p0 = (gkBase + 0 <= gq) ? __expf(s[i][0] * 0.125f) : 0.f;
            float p1 = (gkBase + 1 <= gq) ? __expf(s[i][1] * 0.125f) : 0.f;
            float p2 = (gkBase + 2 <= gq) ? __expf(s[i][2] * 0.125f) : 0.f;
            float p3 = (gkBase + 3 <= gq) ? __expf(s[i][3] * 0.125f) : 0.f;
            pv.x = p0; pv.y = p1; pv.z = p2; pv.w = p3;
            lsum[i] += p0 + p1 + p2 + p3;
            Ps[(ty * 4 + i) * 64 + tx * 4 + 0] = p0;
            Ps[(ty * 4 + i) * 64 + tx * 4 + 1] = p1;
            Ps[(ty * 4 + i) * 64 + tx * 4 + 2] = p2;
            Ps[(ty * 4 + i) * 64 + tx * 4 + 3] = p3;
            *(float4*)&d_attn[((size_t)bh * SS + gq) * SS + gkBase] = pv;
        }
        __syncthreads();

        const float* Vg = g_V + ((size_t)bh * SS + kt * 64) * HEADD;
#pragma unroll
        for (int t = 0; t < 4; t++) {
            int f4 = tid + t * 256;
            int key = f4 >> 4;
            int hd = (f4 & 15) << 2;
            *(float4*)&KVs[key * 64 + hd] = *(const float4*)&Vg[key * 64 + hd];
        }
        __syncthreads();

#pragma unroll
        for (int kk = 0; kk < 64; kk++) {
            float4 bb = *(float4*)&KVs[kk * 64 + tx * 4];
            float a0 = Ps[(ty * 4 + 0) * 64 + kk];
            float a1 = Ps[(ty * 4 + 1) * 64 + kk];
            float a2 = Ps[(ty * 4 + 2) * 64 + kk];
            float a3 = Ps[(ty * 4 + 3) * 64 + kk];
            o[0][0] += a0 * bb.x; o[0][1] += a0 * bb.y; o[0][2] += a0 * bb.z; o[0][3] += a0 * bb.w;
            o[1][0] += a1 * bb.x; o[1][1] += a1 * bb.y; o[1][2] += a1 * bb.z; o[1][3] += a1 * bb.w;
            o[2][0] += a2 * bb.x; o[2][1] += a2 * bb.y; o[2][2] += a2 * bb.z; o[2][3] += a2 * bb.w;
            o[3][0] += a3 * bb.x; o[3][1] += a3 * bb.y; o[3][2] += a3 * bb.z; o[3][3] += a3 * bb.w;
        }
    }

    {
        float4 z = make_float4(0.f, 0.f, 0.f, 0.f);
        for (int kt = qt + 1; kt < SS / 64; kt++) {
#pragma unroll
            for (int i = 0; i < 4; i++) {
                int gq = qt * 64 + ty * 4 + i;
                *(float4*)&d_attn[((size_t)bh * SS + gq) * SS + kt * 64 + tx * 4] = z;
            }
        }
    }

    __syncthreads();
#pragma unroll
    for (int i = 0; i < 4; i++) Ps[(ty * 4 + i) * 16 + tx] = lsum[i];
    __syncthreads();

    const int b = bh >> 4;
    const int h = bh & 15;
#pragma unroll
    for (int i = 0; i < 4; i++) {
        float tot = 0.f;
#pragma unroll
        for (int t = 0; t < 16; t++) tot += Ps[(ty * 4 + i) * 16 + t];
        float inv = 1.f / tot;
        int srow = qt * 64 + ty * 4 + i;
        if (tx == 0) g_L[(size_t)bh * SS + srow] = tot;
        float4 v;
        v.x = o[i][0] * inv;
        v.y = o[i][1] * inv;
        v.z = o[i][2] * inv;
        v.w = o[i][3] * inv;
        *(float4*)&g_Ob[((size_t)b * SS + srow) * DD + h * 64 + tx * 4] = v;
    }
}

// ---------------------------------------------------------------------------
__global__ void rescale_kernel(float* __restrict__ d_attn)
{
    size_t row = blockIdx.x;
    int q = (int)(row & (SS - 1));
    float inv = 1.f / g_L[row];
    int limit = ((q >> 6) + 1) << 6;
    float* p = d_attn + row * SS;
    for (int k = threadIdx.x * 4; k < limit; k += blockDim.x * 4) {
        float4 v = *(float4*)&p[k];
        v.x *= inv; v.y *= inv; v.z *= inv; v.w *= inv;
        *(float4*)&p[k] = v;
    }
}

// ---------------------------------------------------------------------------
extern "C" void kernel_launch(void* const* d_in, const int* in_sizes, int n_in,
                              void* d_out, int out_size)
{
    const float* queries = (const float*)d_in[0];
    const float* keys    = (const float*)d_in[1];
    const float* values  = (const float*)d_in[2];
    // d_in[3] = attn_mask (bool, causal) — applied analytically
    const float* wq = (const float*)d_in[4];
    const float* bq = (const float*)d_in[5];
    const float* wk = (const float*)d_in[6];
    const float* bk = (const float*)d_in[7];
    const float* wv = (const float*)d_in[8];
    const float* bv = (const float*)d_in[9];
    const float* wo = (const float*)d_in[10];
    const float* bo = (const float*)d_in[11];

    float* out   = (float*)d_out;
    float* attnW = out + OUT_ELEMS;

    cudaFuncSetAttribute(gemm_tc, cudaFuncAttributeMaxDynamicSharedMemorySize, GT_SMEM);

    const int nX4 = MROWS * DD / 4;   // 1048576
    const int nW4 = DD * DD / 4;      // 262144
    dim3 gg(DD / 128, MROWS / 128);   // (8, 32) = 256 CTAs

    // Q projection
    cvt_kernel<<<nX4 / 256, 256>>>((const float4*)queries, 0, nX4);
    cvt_kernel<<<nW4 / 256, 256>>>((const float4*)wq, 1, nW4);
    gemm_tc<<<gg, GT_THREADS, GT_SMEM>>>(bq, nullptr, 0);
    // K projection
    cvt_kernel<<<nX4 / 256, 256>>>((const float4*)keys, 0, nX4);
    cvt_kernel<<<nW4 / 256, 256>>>((const float4*)wk, 1, nW4);
    gemm_tc<<<gg, GT_THREADS, GT_SMEM>>>(bk, nullptr, 1);
    // V projection
    cvt_kernel<<<nX4 / 256, 256>>>((const float4*)values, 0, nX4);
    cvt_kernel<<<nW4 / 256, 256>>>((const float4*)wv, 1, nW4);
    gemm_tc<<<gg, GT_THREADS, GT_SMEM>>>(bv, nullptr, 2);

    // Attention
    dim3 ga(SS / 64, BB * HH);
    attn_kernel<<<ga, 256>>>(attnW);
    rescale_kernel<<<BB * HH * SS, 256>>>(attnW);

    // Output projection
    cvt_kernel<<<nX4 / 256, 256>>>(nullptr, 0, nX4);
    cvt_kernel<<<nW4 / 256, 256>>>((const float4*)wo, 1, nW4);
    gemm_tc<<<gg, GT_THREADS, GT_SMEM>>>(bo, out, 3);
}

// round 4
// speedup vs baseline: 2.5678x; 1.7978x over previous
#include <cuda_runtime.h>
#include <cuda_bf16.h>
#include <cstdint>

// Problem constants
#define BB 2
#define SS 2048
#define DD 1024
#define HH 16
#define HEADD 64
#define MROWS (BB*SS)                  // 4096
#define OUT_ELEMS ((size_t)BB*SS*DD)   // 4,194,304

// Scratch (device globals; no allocation allowed)
__device__ float g_Ob[(size_t)BB*SS*DD];
__device__ float g_L[(size_t)BB*HH*SS];
// bf16 hi/lo split buffers for the projection GEMM inputs
__device__ __nv_bfloat16 g_Xh[(size_t)MROWS*DD];
__device__ __nv_bfloat16 g_Xl[(size_t)MROWS*DD];
__device__ __nv_bfloat16 g_Wh[(size_t)DD*DD];
__device__ __nv_bfloat16 g_Wl[(size_t)DD*DD];
// Q/K/V stored as bf16 hi/lo splits, layout [bh][s][64] (Q pre-scaled by log2e/8)
__device__ __nv_bfloat16 g_Qh[(size_t)BB*HH*SS*HEADD];
__device__ __nv_bfloat16 g_Ql[(size_t)BB*HH*SS*HEADD];
__device__ __nv_bfloat16 g_Kh[(size_t)BB*HH*SS*HEADD];
__device__ __nv_bfloat16 g_Kl[(size_t)BB*HH*SS*HEADD];
__device__ __nv_bfloat16 g_Vh[(size_t)BB*HH*SS*HEADD];
__device__ __nv_bfloat16 g_Vl[(size_t)BB*HH*SS*HEADD];

// ---------------------------------------------------------------------------
// Helpers (plain sm_103-safe: mma.sync + ldmatrix, sm_80 ISA)
// ---------------------------------------------------------------------------
__device__ __forceinline__ uint32_t smem_to_u32(const void* p) {
    uint32_t a;
    asm("{ .reg .u64 t; cvta.to.shared.u64 t, %1; cvt.u32.u64 %0, t; }"
        : "=r"(a) : "l"(p));
    return a;
}
__device__ __forceinline__ void ldsm4(uint32_t* r, uint32_t addr) {
    asm volatile("ldmatrix.sync.aligned.m8n8.x4.shared.b16 {%0,%1,%2,%3}, [%4];"
        : "=r"(r[0]), "=r"(r[1]), "=r"(r[2]), "=r"(r[3]) : "r"(addr));
}
__device__ __forceinline__ void ldsm4t(uint32_t* r, uint32_t addr) {
    asm volatile("ldmatrix.sync.aligned.m8n8.x4.trans.shared.b16 {%0,%1,%2,%3}, [%4];"
        : "=r"(r[0]), "=r"(r[1]), "=r"(r[2]), "=r"(r[3]) : "r"(addr));
}
__device__ __forceinline__ void mma_bf16(float* c, const uint32_t* a, const uint32_t* b) {
    asm volatile(
        "mma.sync.aligned.m16n8k16.row.col.f32.bf16.bf16.f32 "
        "{%0,%1,%2,%3}, {%4,%5,%6,%7}, {%8,%9}, {%0,%1,%2,%3};"
        : "+f"(c[0]), "+f"(c[1]), "+f"(c[2]), "+f"(c[3])
        : "r"(a[0]), "r"(a[1]), "r"(a[2]), "r"(a[3]), "r"(b[0]), "r"(b[1]));
}
// pack two f32 -> bf16x2 (lo in low half)
__device__ __forceinline__ uint32_t cvt2bf(float lo, float hi) {
    uint32_t d;
    asm("cvt.rn.bf16x2.f32 %0, %1, %2;" : "=r"(d) : "f"(hi), "f"(lo));
    return d;
}
__device__ __forceinline__ float ex2f(float x) {
    float r; asm("ex2.approx.f32 %0, %1;" : "=f"(r) : "f"(x)); return r;
}

// ---------------------------------------------------------------------------
// fp32 -> bf16 hi/lo split conversion (GEMM inputs).
// dst_sel 0 -> g_Xh/g_Xl ; 1 -> g_Wh/g_Wl.  src==nullptr -> read g_Ob.
// ---------------------------------------------------------------------------
__global__ void cvt_kernel(const float4* __restrict__ src, int dst_sel, int n4)
{
    int i = blockIdx.x * blockDim.x + threadIdx.x;
    if (i >= n4) return;
    const float4* s = src ? src : (const float4*)g_Ob;
    float4 v = s[i];
    uint32_t H0 = cvt2bf(v.x, v.y);
    uint32_t H1 = cvt2bf(v.z, v.w);
    float h0 = __uint_as_float(H0 << 16), h1 = __uint_as_float(H0 & 0xFFFF0000u);
    float h2 = __uint_as_float(H1 << 16), h3 = __uint_as_float(H1 & 0xFFFF0000u);
    uint32_t L0 = cvt2bf(v.x - h0, v.y - h1);
    uint32_t L1 = cvt2bf(v.z - h2, v.w - h3);
    uint2 H = make_uint2(H0, H1), L = make_uint2(L0, L1);
    ((uint2*)(dst_sel ? g_Wh : g_Xh))[i] = H;
    ((uint2*)(dst_sel ? g_Wl : g_Xl))[i] = L;
}

// ---------------------------------------------------------------------------
// HMMA GEMM: Y[4096,1024] = X @ W^T + bias, 3-pass bf16 split, fp32 acc.
// CTA tile 128x128, K chunk 64. 8 warps = 2(m) x 4(n), each warp 64x32.
// mode 0/1/2: emit bf16 hi/lo split to g_{Q,K,V}{h,l} [bh][s][64]
//             (mode 0 additionally scales by log2e/8 for base-2 softmax).
// mode 3: row-major fp32 Yout.
// ---------------------------------------------------------------------------
#define GT_THREADS 256
#define OFF_AL 16384
#define OFF_BH 32768
#define OFF_BL 49152
#define GT_SMEM 65536

__global__ void __launch_bounds__(GT_THREADS, 1)
gemm_tc(const float* __restrict__ bias, float* __restrict__ Yout, int mode)
{
    extern __shared__ char smem[];
    const uint32_t sbase = smem_to_u32(smem);
    const int tid = threadIdx.x;
    const int wid = tid >> 5;
    const int lane = tid & 31;
    const int wm = wid & 1;
    const int wn = wid >> 1;
    const int m0 = blockIdx.y * 128;
    const int n0 = blockIdx.x * 128;

    float acc[4][4][4];
#pragma unroll
    for (int i = 0; i < 4; i++)
#pragma unroll
        for (int j = 0; j < 4; j++)
#pragma unroll
            for (int k = 0; k < 4; k++) acc[i][j][k] = 0.f;

    const int aRow = wm * 64 + (lane & 15);
    const int aSel = lane >> 4;
    const int bRow = wn * 32 + (lane & 7) + ((lane >> 4) << 3);
    const int bSel = (lane >> 3) & 1;

    for (int c = 0; c < 16; c++) {
        const int k0 = c * 64;
#pragma unroll
        for (int t = 0; t < 4; t++) {
            int i = tid + t * GT_THREADS;
            int r = i >> 3, u = i & 7;
            int sw = r * 128 + ((u ^ (r & 7)) << 4);
            size_t gx = (size_t)(m0 + r) * DD + k0 + u * 8;
            size_t gw = (size_t)(n0 + r) * DD + k0 + u * 8;
            *(uint4*)(smem + sw)          = *(const uint4*)(g_Xh + gx);
            *(uint4*)(smem + OFF_AL + sw) = *(const uint4*)(g_Xl + gx);
            *(uint4*)(smem + OFF_BH + sw) = *(const uint4*)(g_Wh + gw);
            *(uint4*)(smem + OFF_BL + sw) = *(const uint4*)(g_Wl + gw);
        }
        __syncthreads();

#pragma unroll
        for (int ks = 0; ks < 4; ks++) {
            uint32_t ah[4][4], al[4][4], bh[2][4], bl[2][4];
#pragma unroll
            for (int mf = 0; mf < 4; mf++) {
                uint32_t addr = sbase + (uint32_t)(aRow + mf * 16) * 128
                              + (uint32_t)(((ks * 2 + aSel) ^ ((aRow + mf * 16) & 7)) << 4);
                ldsm4(ah[mf], addr);
                ldsm4(al[mf], addr + OFF_AL);
            }
#pragma unroll
            for (int p = 0; p < 2; p++) {
                uint32_t addr = sbase + OFF_BH + (uint32_t)(bRow + p * 16) * 128
                              + (uint32_t)(((ks * 2 + bSel) ^ ((bRow + p * 16) & 7)) << 4);
                ldsm4(bh[p], addr);
                ldsm4(bl[p], addr + (OFF_BL - OFF_BH));
            }
#pragma unroll
            for (int mf = 0; mf < 4; mf++) {
#pragma unroll
                for (int nf = 0; nf < 4; nf++) {
                    const int p = nf >> 1, q = (nf & 1) * 2;
                    mma_bf16(acc[mf][nf], ah[mf], &bh[p][q]);
                    mma_bf16(acc[mf][nf], ah[mf], &bl[p][q]);
                    mma_bf16(acc[mf][nf], al[mf], &bh[p][q]);
                }
            }
        }
        __syncthreads();
    }

    // ---- epilogue ----
    if (mode == 3) {
#pragma unroll
        for (int nf = 0; nf < 4; nf++) {
            const int n = n0 + wn * 32 + nf * 8 + (lane & 3) * 2;
            const float bv0 = bias[n], bv1 = bias[n + 1];
#pragma unroll
            for (int mf = 0; mf < 4; mf++) {
                const int m = m0 + wm * 64 + mf * 16 + (lane >> 2);
                float2 v0, v1;
                v0.x = acc[mf][nf][0] + bv0; v0.y = acc[mf][nf][1] + bv1;
                v1.x = acc[mf][nf][2] + bv0; v1.y = acc[mf][nf][3] + bv1;
                *(float2*)&Yout[(size_t)m * DD + n] = v0;
                *(float2*)&Yout[(size_t)(m + 8) * DD + n] = v1;
            }
        }
    } else {
        __nv_bfloat16* dh = (mode == 0) ? g_Qh : (mode == 1) ? g_Kh : g_Vh;
        __nv_bfloat16* dl = (mode == 0) ? g_Ql : (mode == 1) ? g_Kl : g_Vl;
        // log2(e)/8: folds the 1/sqrt(64) scale and base-2 exp into Q
        const float qs = (mode == 0) ? 0.18033688011112042f : 1.0f;
#pragma unroll
        for (int nf = 0; nf < 4; nf++) {
            const int n = n0 + wn * 32 + nf * 8 + (lane & 3) * 2;
            const float bv0 = bias[n], bv1 = bias[n + 1];
            const int h = n >> 6, hd = n & 63;
#pragma unroll
            for (int mf = 0; mf < 4; mf++) {
                const int m = m0 + wm * 64 + mf * 16 + (lane >> 2);
                const int b = m >> 11, s = m & 2047;
                float v0x = (acc[mf][nf][0] + bv0) * qs;
                float v0y = (acc[mf][nf][1] + bv1) * qs;
                float v1x = (acc[mf][nf][2] + bv0) * qs;
                float v1y = (acc[mf][nf][3] + bv1) * qs;
                uint32_t H0 = cvt2bf(v0x, v0y);
                uint32_t H1 = cvt2bf(v1x, v1y);
                float h0l = __uint_as_float(H0 << 16), h0h = __uint_as_float(H0 & 0xFFFF0000u);
                float h1l = __uint_as_float(H1 << 16), h1h = __uint_as_float(H1 & 0xFFFF0000u);
                uint32_t L0 = cvt2bf(v0x - h0l, v0y - h0h);
                uint32_t L1 = cvt2bf(v1x - h1l, v1y - h1h);
                size_t off = ((size_t)(b * HH + h) * SS + s) * 32 + (hd >> 1);
                ((uint32_t*)dh)[off] = H0;
                ((uint32_t*)dl)[off] = L0;
                ((uint32_t*)dh)[off + 256] = H1;   // row s+8
                ((uint32_t*)dl)[off + 256] = L1;
            }
        }
    }
}

// ---------------------------------------------------------------------------
// HMMA attention: CTA = (bh, 128 q-rows), k-tiles of 64.
// S = QhKh+QhKl+QlKh; p = 2^S (scale folded into Q); P repacked to bf16
// A-fragments in registers; O += PhVh+PhVl+PlVh.  Writes unnormalized P to
// d_attn, row sums to g_L, normalized O to g_Ob.
// ---------------------------------------------------------------------------
#define ATTN_SMEM 65536
#define AQH 0
#define AQL 16384
#define AKH 32768
#define AKL 40960
#define AVH 49152
#define AVL 57344

__global__ void __launch_bounds__(256, 1) attn_tc(float* __restrict__ d_attn)
{
    extern __shared__ char smem[];
    const uint32_t sbase = smem_to_u32(smem);
    const int bh = blockIdx.x;
    const int qt = (int)gridDim.y - 1 - (int)blockIdx.y;   // big tiles first
    const int tid = threadIdx.x;
    const int wid = tid >> 5;
    const int lane = tid & 31;
    const int g = lane >> 2, t = lane & 3;
    const int qbase = qt * 128;

    // ---- load Q tiles (hi/lo), 128 rows x 128B, swizzled ----
    {
        const uint4* srcH = (const uint4*)g_Qh + ((size_t)bh * SS + qbase) * 8;
        const uint4* srcL = (const uint4*)g_Ql + ((size_t)bh * SS + qbase) * 8;
#pragma unroll
        for (int j = 0; j < 4; j++) {
            int i = tid + j * 256;
            int r = i >> 3, u = i & 7;
            int sw = r * 128 + ((u ^ (r & 7)) << 4);
            *(uint4*)(smem + AQH + sw) = srcH[r * 8 + u];
            *(uint4*)(smem + AQL + sw) = srcL[r * 8 + u];
        }
    }

    float o[8][4];
#pragma unroll
    for (int f = 0; f < 8; f++)
#pragma unroll
        for (int k = 0; k < 4; k++) o[f][k] = 0.f;
    float rs0 = 0.f, rs1 = 0.f;

    const int aRow = wid * 16 + (lane & 15);
    const int aSel = lane >> 4;
    const int bRowB = (lane & 7) + ((lane >> 4) << 3);
    const int bSel = (lane >> 3) & 1;
    const int vRowB = (lane & 7) + (((lane >> 3) & 1) << 3);
    const int vSel = lane >> 4;

    const int q0 = qbase + wid * 16 + g;
    const int q1 = q0 + 8;
    float* attn0 = d_attn + ((size_t)bh * SS + q0) * SS;
    float* attn1 = d_attn + ((size_t)bh * SS + q1) * SS;

    const int nkt = 2 * qt + 2;
    for (int kt = 0; kt < nkt; kt++) {
        __syncthreads();
        // ---- load K/V hi/lo tiles (64 rows x 128B each) ----
        {
            size_t rb = ((size_t)bh * SS + kt * 64) * 8;
#pragma unroll
            for (int j = 0; j < 2; j++) {
                int i = tid + j * 256;
                int r = i >> 3, u = i & 7;
                int sw = r * 128 + ((u ^ (r & 7)) << 4);
                *(uint4*)(smem + AKH + sw) = ((const uint4*)g_Kh)[rb + r * 8 + u];
                *(uint4*)(smem + AKL + sw) = ((const uint4*)g_Kl)[rb + r * 8 + u];
                *(uint4*)(smem + AVH + sw) = ((const uint4*)g_Vh)[rb + r * 8 + u];
                *(uint4*)(smem + AVL + sw) = ((const uint4*)g_Vl)[rb + r * 8 + u];
            }
        }
        __syncthreads();

        // ---- S = Q K^T (3-pass split), 16x64 per warp ----
        float s[8][4];
#pragma unroll
        for (int f = 0; f < 8; f++)
#pragma unroll
            for (int k = 0; k < 4; k++) s[f][k] = 0.f;

#pragma unroll
        for (int ks = 0; ks < 4; ks++) {
            uint32_t ah[4], al[4];
            uint32_t addrA = sbase + AQH + (uint32_t)aRow * 128
                           + (uint32_t)((((ks << 1) + aSel) ^ (aRow & 7)) << 4);
            ldsm4(ah, addrA);
            ldsm4(al, addrA + (AQL - AQH));
#pragma unroll
            for (int p = 0; p < 4; p++) {
                int row = bRowB + p * 16;
                uint32_t addrB = sbase + AKH + (uint32_t)row * 128
                               + (uint32_t)((((ks << 1) + bSel) ^ (row & 7)) << 4);
                uint32_t kh[4], kl[4];
                ldsm4(kh, addrB);
                ldsm4(kl, addrB + (AKL - AKH));
                mma_bf16(s[2 * p],     ah, &kh[0]);
                mma_bf16(s[2 * p + 1], ah, &kh[2]);
                mma_bf16(s[2 * p],     ah, &kl[0]);
                mma_bf16(s[2 * p + 1], ah, &kl[2]);
                mma_bf16(s[2 * p],     al, &kh[0]);
                mma_bf16(s[2 * p + 1], al, &kh[2]);
            }
        }

        // ---- exp (base-2), mask, store P, rowsum, repack to A-frags ----
        const bool full = (kt * 64 + 63) <= (qbase + wid * 16);
        const int kcb = kt * 64 + 2 * t;
        uint32_t pah[4][4], pal[4][4];
#pragma unroll
        for (int f = 0; f < 8; f++) {
            int kc = kcb + 8 * f;
            float p0 = ex2f(s[f][0]);
            float p1 = ex2f(s[f][1]);
            float p2 = ex2f(s[f][2]);
            float p3 = ex2f(s[f][3]);
            if (!full) {
                p0 = (kc     <= q0) ? p0 : 0.f;
                p1 = (kc + 1 <= q0) ? p1 : 0.f;
                p2 = (kc     <= q1) ? p2 : 0.f;
                p3 = (kc + 1 <= q1) ? p3 : 0.f;
            }
            rs0 += p0 + p1;
            rs1 += p2 + p3;
            float2 w0, w1;
            w0.x = p0; w0.y = p1; w1.x = p2; w1.y = p3;
            *(float2*)&attn0[kc] = w0;
            *(float2*)&attn1[kc] = w1;
            uint32_t H0 = cvt2bf(p0, p1);
            uint32_t H1 = cvt2bf(p2, p3);
            float h0 = __uint_as_float(H0 << 16), h1 = __uint_as_float(H0 & 0xFFFF0000u);
            float h2 = __uint_as_float(H1 << 16), h3 = __uint_as_float(H1 & 0xFFFF0000u);
            uint32_t L0 = cvt2bf(p0 - h0, p1 - h1);
            uint32_t L1 = cvt2bf(p2 - h2, p3 - h3);
            int ks = f >> 1, o2 = (f & 1) << 1;
            pah[ks][o2] = H0; pah[ks][o2 + 1] = H1;
            pal[ks][o2] = L0; pal[ks][o2 + 1] = L1;
        }

        // ---- O += P V (3-pass split) ----
#pragma unroll
        for (int ks = 0; ks < 4; ks++) {
            int row = vRowB + ks * 16;
#pragma unroll
            for (int p = 0; p < 4; p++) {
                int cu = p * 2 + vSel;
                uint32_t addrV = sbase + AVH + (uint32_t)row * 128
                               + (uint32_t)((cu ^ (row & 7)) << 4);
                uint32_t vh[4], vl[4];
                ldsm4t(vh, addrV);
                ldsm4t(vl, addrV + (AVL - AVH));
                mma_bf16(o[2 * p],     pah[ks], &vh[0]);
                mma_bf16(o[2 * p + 1], pah[ks], &vh[2]);
                mma_bf16(o[2 * p],     pah[ks], &vl[0]);
                mma_bf16(o[2 * p + 1], pah[ks], &vl[2]);
                mma_bf16(o[2 * p],     pal[ks], &vh[0]);
                mma_bf16(o[2 * p + 1], pal[ks], &vh[2]);
            }
        }
    }

    // ---- row sums (reduce across the 4 lanes of each row), normalize, store ----
    rs0 += __shfl_xor_sync(0xFFFFFFFFu, rs0, 1);
    rs0 += __shfl_xor_sync(0xFFFFFFFFu, rs0, 2);
    rs1 += __shfl_xor_sync(0xFFFFFFFFu, rs1, 1);
    rs1 += __shfl_xor_sync(0xFFFFFFFFu, rs1, 2);
    if (t == 0) {
        g_L[(size_t)bh * SS + q0] = rs0;
        g_L[(size_t)bh * SS + q1] = rs1;
    }
    const float inv0 = 1.f / rs0, inv1 = 1.f / rs1;
    const int b = bh >> 4, h = bh & 15;
    float* ob0 = g_Ob + ((size_t)b * SS + q0) * DD + h * 64;
    float* ob1 = g_Ob + ((size_t)b * SS + q1) * DD + h * 64;
#pragma unroll
    for (int f = 0; f < 8; f++) {
        int col = 8 * f + 2 * t;
        float2 v0, v1;
        v0.x = o[f][0] * inv0; v0.y = o[f][1] * inv0;
        v1.x = o[f][2] * inv1; v1.y = o[f][3] * inv1;
        *(float2*)&ob0[col] = v0;
        *(float2*)&ob1[col] = v1;
    }
}

// ---------------------------------------------------------------------------
// Rescale lower triangle by 1/L and zero-fill the upper triangle.
// ---------------------------------------------------------------------------
__global__ void rescale_kernel(float* __restrict__ d_attn)
{
    size_t row = blockIdx.x;
    int q = (int)(row & (SS - 1));
    float inv = 1.f / g_L[row];
    int limit = ((q >> 7) + 1) << 7;   // 128-row q-tiles
    float* p = d_attn + row * SS;
    for (int k = threadIdx.x * 4; k < limit; k += 1024) {
        float4 v = *(float4*)&p[k];
        v.x *= inv; v.y *= inv; v.z *= inv; v.w *= inv;
        *(float4*)&p[k] = v;
    }
    float4 z = make_float4(0.f, 0.f, 0.f, 0.f);
    for (int k = limit + threadIdx.x * 4; k < SS; k += 1024) {
        *(float4*)&p[k] = z;
    }
}

// ---------------------------------------------------------------------------
extern "C" void kernel_launch(void* const* d_in, const int* in_sizes, int n_in,
                              void* d_out, int out_size)
{
    const float* queries = (const float*)d_in[0];
    const float* keys    = (const float*)d_in[1];
    const float* values  = (const float*)d_in[2];
    // d_in[3] = attn_mask (bool, causal) — applied analytically
    const float* wq = (const float*)d_in[4];
    const float* bq = (const float*)d_in[5];
    const float* wk = (const float*)d_in[6];
    const float* bk = (const float*)d_in[7];
    const float* wv = (const float*)d_in[8];
    const float* bv = (const float*)d_in[9];
    const float* wo = (const float*)d_in[10];
    const float* bo = (const float*)d_in[11];

    float* out   = (float*)d_out;
    float* attnW = out + OUT_ELEMS;

    cudaFuncSetAttribute(gemm_tc, cudaFuncAttributeMaxDynamicSharedMemorySize, GT_SMEM);
    cudaFuncSetAttribute(attn_tc, cudaFuncAttributeMaxDynamicSharedMemorySize, ATTN_SMEM);

    const int nX4 = MROWS * DD / 4;
    const int nW4 = DD * DD / 4;
    dim3 gg(DD / 128, MROWS / 128);   // (8, 32) = 256 CTAs

    // Q projection (scaled by log2e/8, split bf16)
    cvt_kernel<<<nX4 / 256, 256>>>((const float4*)queries, 0, nX4);
    cvt_kernel<<<nW4 / 256, 256>>>((const float4*)wq, 1, nW4);
    gemm_tc<<<gg, GT_THREADS, GT_SMEM>>>(bq, nullptr, 0);
    // K projection
    cvt_kernel<<<nX4 / 256, 256>>>((const float4*)keys, 0, nX4);
    cvt_kernel<<<nW4 / 256, 256>>>((const float4*)wk, 1, nW4);
    gemm_tc<<<gg, GT_THREADS, GT_SMEM>>>(bk, nullptr, 1);
    // V projection
    cvt_kernel<<<nX4 / 256, 256>>>((const float4*)values, 0, nX4);
    cvt_kernel<<<nW4 / 256, 256>>>((const float4*)wv, 1, nW4);
    gemm_tc<<<gg, GT_THREADS, GT_SMEM>>>(bv, nullptr, 2);

    // Attention (HMMA)
    dim3 ga(BB * HH, SS / 128);       // (32, 16)
    attn_tc<<<ga, 256, ATTN_SMEM>>>(attnW);
    rescale_kernel<<<BB * HH * SS, 256>>>(attnW);

    // Output projection
    cvt_kernel<<<nX4 / 256, 256>>>(nullptr, 0, nX4);
    cvt_kernel<<<nW4 / 256, 256>>>((const float4*)wo, 1, nW4);
    gemm_tc<<<gg, GT_THREADS, GT_SMEM>>>(bo, out, 3);
}

// round 5
// speedup vs baseline: 3.0592x; 1.1914x over previous
#include <cuda_runtime.h>
#include <cuda_bf16.h>
#include <cstdint>

// Problem constants
#define BB 2
#define SS 2048
#define DD 1024
#define HH 16
#define HEADD 64
#define MROWS (BB*SS)                  // 4096
#define OUT_ELEMS ((size_t)BB*SS*DD)   // 4,194,304
#define XSZ ((size_t)MROWS*DD)         // 4M elements
#define WSZ ((size_t)DD*DD)            // 1M elements

// Scratch (device globals; no allocation allowed)
__device__ float g_Ob[(size_t)BB*SS*DD];
// bf16 hi/lo split inputs: X slots 0..2 (queries/keys/values or Ob in slot 0)
__device__ __nv_bfloat16 g_Xh[3*XSZ];
__device__ __nv_bfloat16 g_Xl[3*XSZ];
// W slots 0..3 (wq,wk,wv,wo)
__device__ __nv_bfloat16 g_Wh[4*WSZ];
__device__ __nv_bfloat16 g_Wl[4*WSZ];
// Q/K/V bf16 hi/lo splits, layout [bh][s][64] (Q pre-scaled by log2e/8)
__device__ __nv_bfloat16 g_Qh[(size_t)BB*HH*SS*HEADD];
__device__ __nv_bfloat16 g_Ql[(size_t)BB*HH*SS*HEADD];
__device__ __nv_bfloat16 g_Kh[(size_t)BB*HH*SS*HEADD];
__device__ __nv_bfloat16 g_Kl[(size_t)BB*HH*SS*HEADD];
__device__ __nv_bfloat16 g_Vh[(size_t)BB*HH*SS*HEADD];
__device__ __nv_bfloat16 g_Vl[(size_t)BB*HH*SS*HEADD];

// ---------------------------------------------------------------------------
// Helpers (plain sm_103-safe: mma.sync + ldmatrix + cp.async, sm_80 ISA)
// ---------------------------------------------------------------------------
__device__ __forceinline__ uint32_t smem_to_u32(const void* p) {
    uint32_t a;
    asm("{ .reg .u64 t; cvta.to.shared.u64 t, %1; cvt.u32.u64 %0, t; }"
        : "=r"(a) : "l"(p));
    return a;
}
__device__ __forceinline__ void ldsm4(uint32_t* r, uint32_t addr) {
    asm volatile("ldmatrix.sync.aligned.m8n8.x4.shared.b16 {%0,%1,%2,%3}, [%4];"
        : "=r"(r[0]), "=r"(r[1]), "=r"(r[2]), "=r"(r[3]) : "r"(addr));
}
__device__ __forceinline__ void ldsm4t(uint32_t* r, uint32_t addr) {
    asm volatile("ldmatrix.sync.aligned.m8n8.x4.trans.shared.b16 {%0,%1,%2,%3}, [%4];"
        : "=r"(r[0]), "=r"(r[1]), "=r"(r[2]), "=r"(r[3]) : "r"(addr));
}
__device__ __forceinline__ void mma_bf16(float* c, const uint32_t* a, const uint32_t* b) {
    asm volatile(
        "mma.sync.aligned.m16n8k16.row.col.f32.bf16.bf16.f32 "
        "{%0,%1,%2,%3}, {%4,%5,%6,%7}, {%8,%9}, {%0,%1,%2,%3};"
        : "+f"(c[0]), "+f"(c[1]), "+f"(c[2]), "+f"(c[3])
        : "r"(a[0]), "r"(a[1]), "r"(a[2]), "r"(a[3]), "r"(b[0]), "r"(b[1]));
}
__device__ __forceinline__ uint32_t cvt2bf(float lo, float hi) {
    uint32_t d;
    asm("cvt.rn.bf16x2.f32 %0, %1, %2;" : "=r"(d) : "f"(hi), "f"(lo));
    return d;
}
__device__ __forceinline__ float ex2f(float x) {
    float r; asm("ex2.approx.f32 %0, %1;" : "=f"(r) : "f"(x)); return r;
}
__device__ __forceinline__ void cpasync16(uint32_t saddr, const void* g) {
    asm volatile("cp.async.cg.shared.global [%0], [%1], 16;" :: "r"(saddr), "l"(g));
}
#define CP_COMMIT asm volatile("cp.async.commit_group;" ::: "memory")
#define CP_WAIT1  asm volatile("cp.async.wait_group 1;" ::: "memory")
#define CP_WAIT0  asm volatile("cp.async.wait_group 0;" ::: "memory")

// ---------------------------------------------------------------------------
// Convert all GEMM inputs in ONE launch:
//  blocks [0,12288): queries/keys/values -> X slots 0/1/2
//  blocks [12288,16384): wq/wk/wv/wo     -> W slots 0/1/2/3
// ---------------------------------------------------------------------------
__global__ void cvt_all(const float4* __restrict__ q, const float4* __restrict__ k,
                        const float4* __restrict__ v,
                        const float4* __restrict__ wq, const float4* __restrict__ wk,
                        const float4* __restrict__ wv, const float4* __restrict__ wo)
{
    const int blk = blockIdx.x;
    const float4* src;
    uint2 *dh, *dl;
    size_t off;
    if (blk < 12288) {
        int slot = blk >> 12;
        off = (size_t)(blk & 4095) * 256 + threadIdx.x;
        src = (slot == 0) ? q : (slot == 1) ? k : v;
        dh = (uint2*)(g_Xh + slot * XSZ);
        dl = (uint2*)(g_Xl + slot * XSZ);
    } else {
        int b2 = blk - 12288;
        int slot = b2 >> 10;
        off = (size_t)(b2 & 1023) * 256 + threadIdx.x;
        src = (slot == 0) ? wq : (slot == 1) ? wk : (slot == 2) ? wv : wo;
        dh = (uint2*)(g_Wh + slot * WSZ);
        dl = (uint2*)(g_Wl + slot * WSZ);
    }
    float4 x = src[off];
    uint32_t H0 = cvt2bf(x.x, x.y);
    uint32_t H1 = cvt2bf(x.z, x.w);
    float h0 = __uint_as_float(H0 << 16), h1 = __uint_as_float(H0 & 0xFFFF0000u);
    float h2 = __uint_as_float(H1 << 16), h3 = __uint_as_float(H1 & 0xFFFF0000u);
    dh[off] = make_uint2(H0, H1);
    dl[off] = make_uint2(cvt2bf(x.x - h0, x.y - h1), cvt2bf(x.z - h2, x.w - h3));
}

// fp32 g_Ob -> X slot 0 split (for the output projection)
__global__ void cvt_ob(int n4)
{
    int i = blockIdx.x * blockDim.x + threadIdx.x;
    if (i >= n4) return;
    float4 x = ((const float4*)g_Ob)[i];
    uint32_t H0 = cvt2bf(x.x, x.y);
    uint32_t H1 = cvt2bf(x.z, x.w);
    float h0 = __uint_as_float(H0 << 16), h1 = __uint_as_float(H0 & 0xFFFF0000u);
    float h2 = __uint_as_float(H1 << 16), h3 = __uint_as_float(H1 & 0xFFFF0000u);
    ((uint2*)g_Xh)[i] = make_uint2(H0, H1);
    ((uint2*)g_Xl)[i] = make_uint2(cvt2bf(x.x - h0, x.y - h1), cvt2bf(x.z - h2, x.w - h3));
}

// ---------------------------------------------------------------------------
// Projection GEMM: Y = X @ W^T + bias, 3-pass bf16 split, fp32 acc.
// CTA tile 128x128, K chunk 64, cp.async double-buffered (2 x 64KB stages).
// grid.z selects input slot; mode = base_mode + z.
// mode 0/1/2: emit split bf16 Q/K/V [bh][s][64] (mode 0 scaled by log2e/8);
// mode 3: row-major fp32 Yout.
// ---------------------------------------------------------------------------
#define PJ_AH 0
#define PJ_AL 16384
#define PJ_BH 32768
#define PJ_BL 49152
#define PJ_STAGE 65536
#define PJ_SMEM 131072

__global__ void __launch_bounds__(256, 1)
proj_tc(const float* __restrict__ bias0, const float* __restrict__ bias1,
        const float* __restrict__ bias2, float* __restrict__ Yout, int base_mode)
{
    extern __shared__ char smem[];
    const uint32_t sbase = smem_to_u32(smem);
    const int tid = threadIdx.x;
    const int wid = tid >> 5;
    const int lane = tid & 31;
    const int wm = wid & 1;
    const int wn = wid >> 1;
    const int m0 = blockIdx.y * 128;
    const int n0 = blockIdx.x * 128;
    const int z = blockIdx.z;
    const int mode = base_mode + z;
    const int wslot = (mode == 3) ? 3 : z;

    const __nv_bfloat16* Xh = g_Xh + (size_t)z * XSZ;
    const __nv_bfloat16* Xl = g_Xl + (size_t)z * XSZ;
    const __nv_bfloat16* Wh = g_Wh + (size_t)wslot * WSZ;
    const __nv_bfloat16* Wl = g_Wl + (size_t)wslot * WSZ;
    const float* bias = (mode == 3) ? bias0 : ((z == 0) ? bias0 : (z == 1) ? bias1 : bias2);

    float acc[4][4][4];
#pragma unroll
    for (int i = 0; i < 4; i++)
#pragma unroll
        for (int j = 0; j < 4; j++)
#pragma unroll
            for (int k = 0; k < 4; k++) acc[i][j][k] = 0.f;

    const int aRow = wm * 64 + (lane & 15);
    const int aSel = lane >> 4;
    const int bRow = wn * 32 + (lane & 7) + ((lane >> 4) << 3);
    const int bSel = (lane >> 3) & 1;

    auto issue = [&](int c, int st) {
        const uint32_t sb = sbase + st * PJ_STAGE;
        const int k0 = c * 64;
#pragma unroll
        for (int t = 0; t < 4; t++) {
            int i = tid + t * 256;
            int r = i >> 3, u = i & 7;
            int sw = r * 128 + ((u ^ (r & 7)) << 4);
            size_t gx = (size_t)(m0 + r) * DD + k0 + u * 8;
            size_t gw = (size_t)(n0 + r) * DD + k0 + u * 8;
            cpasync16(sb + PJ_AH + sw, Xh + gx);
            cpasync16(sb + PJ_AL + sw, Xl + gx);
            cpasync16(sb + PJ_BH + sw, Wh + gw);
            cpasync16(sb + PJ_BL + sw, Wl + gw);
        }
    };

    issue(0, 0); CP_COMMIT;
    for (int c = 0; c < 16; c++) {
        if (c < 15) { issue(c + 1, (c + 1) & 1); CP_COMMIT; CP_WAIT1; }
        else CP_WAIT0;
        __syncthreads();
        const uint32_t sb = sbase + (c & 1) * PJ_STAGE;
#pragma unroll
        for (int ks = 0; ks < 4; ks++) {
            uint32_t ah[4][4], al[4][4], bh[2][4], bl[2][4];
#pragma unroll
            for (int mf = 0; mf < 4; mf++) {
                int row = aRow + mf * 16;
                uint32_t addr = sb + (uint32_t)row * 128
                              + (uint32_t)(((ks * 2 + aSel) ^ (row & 7)) << 4);
                ldsm4(ah[mf], addr);
                ldsm4(al[mf], addr + PJ_AL);
            }
#pragma unroll
            for (int p = 0; p < 2; p++) {
                int row = bRow + p * 16;
                uint32_t addr = sb + PJ_BH + (uint32_t)row * 128
                              + (uint32_t)(((ks * 2 + bSel) ^ (row & 7)) << 4);
                ldsm4(bh[p], addr);
                ldsm4(bl[p], addr + (PJ_BL - PJ_BH));
            }
#pragma unroll
            for (int mf = 0; mf < 4; mf++) {
#pragma unroll
                for (int nf = 0; nf < 4; nf++) {
                    const int p = nf >> 1, q = (nf & 1) * 2;
                    mma_bf16(acc[mf][nf], ah[mf], &bh[p][q]);
                    mma_bf16(acc[mf][nf], ah[mf], &bl[p][q]);
                    mma_bf16(acc[mf][nf], al[mf], &bh[p][q]);
                }
            }
        }
        __syncthreads();
    }

    // ---- epilogue ----
    if (mode == 3) {
#pragma unroll
        for (int nf = 0; nf < 4; nf++) {
            const int n = n0 + wn * 32 + nf * 8 + (lane & 3) * 2;
            const float bv0 = bias[n], bv1 = bias[n + 1];
#pragma unroll
            for (int mf = 0; mf < 4; mf++) {
                const int m = m0 + wm * 64 + mf * 16 + (lane >> 2);
                float2 v0, v1;
                v0.x = acc[mf][nf][0] + bv0; v0.y = acc[mf][nf][1] + bv1;
                v1.x = acc[mf][nf][2] + bv0; v1.y = acc[mf][nf][3] + bv1;
                *(float2*)&Yout[(size_t)m * DD + n] = v0;
                *(float2*)&Yout[(size_t)(m + 8) * DD + n] = v1;
            }
        }
    } else {
        __nv_bfloat16* dh = (mode == 0) ? g_Qh : (mode == 1) ? g_Kh : g_Vh;
        __nv_bfloat16* dl = (mode == 0) ? g_Ql : (mode == 1) ? g_Kl : g_Vl;
        const float qs = (mode == 0) ? 0.18033688011112042f : 1.0f;  // log2(e)/8
#pragma unroll
        for (int nf = 0; nf < 4; nf++) {
            const int n = n0 + wn * 32 + nf * 8 + (lane & 3) * 2;
            const float bv0 = bias[n], bv1 = bias[n + 1];
            const int h = n >> 6, hd = n & 63;
#pragma unroll
            for (int mf = 0; mf < 4; mf++) {
                const int m = m0 + wm * 64 + mf * 16 + (lane >> 2);
                const int b = m >> 11, s = m & 2047;
                float v0x = (acc[mf][nf][0] + bv0) * qs;
                float v0y = (acc[mf][nf][1] + bv1) * qs;
                float v1x = (acc[mf][nf][2] + bv0) * qs;
                float v1y = (acc[mf][nf][3] + bv1) * qs;
                uint32_t H0 = cvt2bf(v0x, v0y);
                uint32_t H1 = cvt2bf(v1x, v1y);
                float h0l = __uint_as_float(H0 << 16), h0h = __uint_as_float(H0 & 0xFFFF0000u);
                float h1l = __uint_as_float(H1 << 16), h1h = __uint_as_float(H1 & 0xFFFF0000u);
                uint32_t L0 = cvt2bf(v0x - h0l, v0y - h0h);
                uint32_t L1 = cvt2bf(v1x - h1l, v1y - h1h);
                size_t off = ((size_t)(b * HH + h) * SS + s) * 32 + (hd >> 1);
                ((uint32_t*)dh)[off] = H0;
                ((uint32_t*)dl)[off] = L0;
                ((uint32_t*)dh)[off + 256] = H1;   // row s+8
                ((uint32_t*)dl)[off + 256] = L1;
            }
        }
    }
}

// ---------------------------------------------------------------------------
// Two-phase HMMA attention. CTA = (bh, 128 q-rows), k-tiles of 64.
// Phase A: S = QK^T (3-pass split), p = 2^S, accumulate row sums only.
// Phase B: recompute, normalize p, write P (normalized) to d_attn, O += P V.
// Also zero-fills the CTA's upper-triangle strip. No rescale pass needed.
// K/V loads cp.async double-buffered.
// SMEM: Q 32KB | K stages 2x16KB | V stages 2x16KB = 96KB
// ---------------------------------------------------------------------------
#define AQH 0
#define AQL 16384
#define AK0 32768
#define AV0 65536
#define ATTN_SMEM 98304

__global__ void __launch_bounds__(256, 1) attn_tc(float* __restrict__ d_attn)
{
    extern __shared__ char smem[];
    const uint32_t sbase = smem_to_u32(smem);
    const int bh = blockIdx.x;
    const int qt = (int)gridDim.y - 1 - (int)blockIdx.y;   // big tiles first
    const int tid = threadIdx.x;
    const int wid = tid >> 5;
    const int lane = tid & 31;
    const int g = lane >> 2, t = lane & 3;
    const int qbase = qt * 128;
    const int nkt = 2 * qt + 2;

    // ---- load Q tiles (hi/lo), swizzled ----
    {
        const uint4* srcH = (const uint4*)g_Qh + ((size_t)bh * SS + qbase) * 8;
        const uint4* srcL = (const uint4*)g_Ql + ((size_t)bh * SS + qbase) * 8;
#pragma unroll
        for (int j = 0; j < 4; j++) {
            int i = tid + j * 256;
            int r = i >> 3, u = i & 7;
            int sw = r * 128 + ((u ^ (r & 7)) << 4);
            *(uint4*)(smem + AQH + sw) = srcH[r * 8 + u];
            *(uint4*)(smem + AQL + sw) = srcL[r * 8 + u];
        }
    }

    const int aRow = wid * 16 + (lane & 15);
    const int aSel = lane >> 4;
    const int bRowB = (lane & 7) + ((lane >> 4) << 3);
    const int bSel = (lane >> 3) & 1;
    const int vRowB = (lane & 7) + (((lane >> 3) & 1) << 3);
    const int vSel = lane >> 4;

    const int q0 = qbase + wid * 16 + g;
    const int q1 = q0 + 8;

    auto issueK = [&](int kt, int st) {
        size_t rb = ((size_t)bh * SS + kt * 64) * 8;
        uint32_t sb = sbase + AK0 + st * 16384;
#pragma unroll
        for (int j = 0; j < 2; j++) {
            int i = tid + j * 256;
            int r = i >> 3, u = i & 7;
            int sw = r * 128 + ((u ^ (r & 7)) << 4);
            cpasync16(sb + sw, (const uint4*)g_Kh + rb + r * 8 + u);
            cpasync16(sb + 8192 + sw, (const uint4*)g_Kl + rb + r * 8 + u);
        }
    };
    auto issueV = [&](int kt, int st) {
        size_t rb = ((size_t)bh * SS + kt * 64) * 8;
        uint32_t sb = sbase + AV0 + st * 16384;
#pragma unroll
        for (int j = 0; j < 2; j++) {
            int i = tid + j * 256;
            int r = i >> 3, u = i & 7;
            int sw = r * 128 + ((u ^ (r & 7)) << 4);
            cpasync16(sb + sw, (const uint4*)g_Vh + rb + r * 8 + u);
            cpasync16(sb + 8192 + sw, (const uint4*)g_Vl + rb + r * 8 + u);
        }
    };

    // S = Q K^T for one stage (3-pass split)
    auto computeS = [&](int st, float s[8][4]) {
        const uint32_t kb = sbase + AK0 + st * 16384;
#pragma unroll
        for (int f = 0; f < 8; f++)
#pragma unroll
            for (int k = 0; k < 4; k++) s[f][k] = 0.f;
#pragma unroll
        for (int ks = 0; ks < 4; ks++) {
            uint32_t ah[4], al[4];
            uint32_t addrA = sbase + AQH + (uint32_t)aRow * 128
                           + (uint32_t)((((ks << 1) + aSel) ^ (aRow & 7)) << 4);
            ldsm4(ah, addrA);
            ldsm4(al, addrA + (AQL - AQH));
#pragma unroll
            for (int p = 0; p < 4; p++) {
                int row = bRowB + p * 16;
                uint32_t addrB = kb + (uint32_t)row * 128
                               + (uint32_t)((((ks << 1) + bSel) ^ (row & 7)) << 4);
                uint32_t kh[4], kl[4];
                ldsm4(kh, addrB);
                ldsm4(kl, addrB + 8192);
                mma_bf16(s[2 * p],     ah, &kh[0]);
                mma_bf16(s[2 * p + 1], ah, &kh[2]);
                mma_bf16(s[2 * p],     ah, &kl[0]);
                mma_bf16(s[2 * p + 1], ah, &kl[2]);
                mma_bf16(s[2 * p],     al, &kh[0]);
                mma_bf16(s[2 * p + 1], al, &kh[2]);
            }
        }
    };

    // ================= Phase A: row sums =================
    float rs0 = 0.f, rs1 = 0.f;
    issueK(0, 0); CP_COMMIT;
    for (int kt = 0; kt < nkt; kt++) {
        if (kt + 1 < nkt) { issueK(kt + 1, (kt + 1) & 1); CP_COMMIT; CP_WAIT1; }
        else CP_WAIT0;
        __syncthreads();
        float s[8][4];
        computeS(kt & 1, s);
        __syncthreads();   // stage reads done before next overwrite

        const bool full = (kt * 64 + 63) <= (qbase + wid * 16);
        const int kcb = kt * 64 + 2 * t;
#pragma unroll
        for (int f = 0; f < 8; f++) {
            int kc = kcb + 8 * f;
            float p0 = ex2f(s[f][0]);
            float p1 = ex2f(s[f][1]);
            float p2 = ex2f(s[f][2]);
            float p3 = ex2f(s[f][3]);
            if (!full) {
                p0 = (kc     <= q0) ? p0 : 0.f;
                p1 = (kc + 1 <= q0) ? p1 : 0.f;
                p2 = (kc     <= q1) ? p2 : 0.f;
                p3 = (kc + 1 <= q1) ? p3 : 0.f;
            }
            rs0 += p0 + p1;
            rs1 += p2 + p3;
        }
    }
    rs0 += __shfl_xor_sync(0xFFFFFFFFu, rs0, 1);
    rs0 += __shfl_xor_sync(0xFFFFFFFFu, rs0, 2);
    rs1 += __shfl_xor_sync(0xFFFFFFFFu, rs1, 1);
    rs1 += __shfl_xor_sync(0xFFFFFFFFu, rs1, 2);
    const float inv0 = 1.f / rs0, inv1 = 1.f / rs1;

    // ---- zero-fill this CTA's upper-triangle strip ----
    {
        const int zstart = qbase + 128;
        float4 z4 = make_float4(0.f, 0.f, 0.f, 0.f);
        for (int r = 0; r < 128 && zstart < SS; r++) {
            float* rowp = d_attn + ((size_t)bh * SS + qbase + r) * SS;
            for (int kc = zstart + tid * 4; kc < SS; kc += 1024)
                *(float4*)&rowp[kc] = z4;
        }
    }

    // ================= Phase B: normalized P store + O accumulate =========
    float o[8][4];
#pragma unroll
    for (int f = 0; f < 8; f++)
#pragma unroll
        for (int k = 0; k < 4; k++) o[f][k] = 0.f;

    float* attn0 = d_attn + ((size_t)bh * SS + q0) * SS;
    float* attn1 = d_attn + ((size_t)bh * SS + q1) * SS;

    issueK(0, 0); issueV(0, 0); CP_COMMIT;
    for (int kt = 0; kt < nkt; kt++) {
        if (kt + 1 < nkt) {
            issueK(kt + 1, (kt + 1) & 1); issueV(kt + 1, (kt + 1) & 1);
            CP_COMMIT; CP_WAIT1;
        } else CP_WAIT0;
        __syncthreads();

        float s[8][4];
        computeS(kt & 1, s);

        const bool full = (kt * 64 + 63) <= (qbase + wid * 16);
        const int kcb = kt * 64 + 2 * t;
        uint32_t pah[4][4], pal[4][4];
#pragma unroll
        for (int f = 0; f < 8; f++) {
            int kc = kcb + 8 * f;
            float p0 = ex2f(s[f][0]) * inv0;
            float p1 = ex2f(s[f][1]) * inv0;
            float p2 = ex2f(s[f][2]) * inv1;
            float p3 = ex2f(s[f][3]) * inv1;
            if (!full) {
                p0 = (kc     <= q0) ? p0 : 0.f;
                p1 = (kc + 1 <= q0) ? p1 : 0.f;
                p2 = (kc     <= q1) ? p2 : 0.f;
                p3 = (kc + 1 <= q1) ? p3 : 0.f;
            }
            float2 w0, w1;
            w0.x = p0; w0.y = p1; w1.x = p2; w1.y = p3;
            *(float2*)&attn0[kc] = w0;
            *(float2*)&attn1[kc] = w1;
            uint32_t H0 = cvt2bf(p0, p1);
            uint32_t H1 = cvt2bf(p2, p3);
            float h0 = __uint_as_float(H0 << 16), h1 = __uint_as_float(H0 & 0xFFFF0000u);
            float h2 = __uint_as_float(H1 << 16), h3 = __uint_as_float(H1 & 0xFFFF0000u);
            uint32_t L0 = cvt2bf(p0 - h0, p1 - h1);
            uint32_t L1 = cvt2bf(p2 - h2, p3 - h3);
            int ks = f >> 1, o2 = (f & 1) << 1;
            pah[ks][o2] = H0; pah[ks][o2 + 1] = H1;
            pal[ks][o2] = L0; pal[ks][o2 + 1] = L1;
        }

        // O += P V (3-pass split), V from this stage
        const uint32_t vb = sbase + AV0 + (kt & 1) * 16384;
#pragma unroll
        for (int ks = 0; ks < 4; ks++) {
            int row = vRowB + ks * 16;
#pragma unroll
            for (int p = 0; p < 4; p++) {
                int cu = p * 2 + vSel;
                uint32_t addrV = vb + (uint32_t)row * 128
                               + (uint32_t)((cu ^ (row & 7)) << 4);
                uint32_t vh[4], vl[4];
                ldsm4t(vh, addrV);
                ldsm4t(vl, addrV + 8192);
                mma_bf16(o[2 * p],     pah[ks], &vh[0]);
                mma_bf16(o[2 * p + 1], pah[ks], &vh[2]);
                mma_bf16(o[2 * p],     pah[ks], &vl[0]);
                mma_bf16(o[2 * p + 1], pah[ks], &vl[2]);
                mma_bf16(o[2 * p],     pal[ks], &vh[0]);
                mma_bf16(o[2 * p + 1], pal[ks], &vh[2]);
            }
        }
        __syncthreads();   // stage reads done before next overwrite
    }

    // ---- store O (already normalized) ----
    const int b = bh >> 4, h = bh & 15;
    float* ob0 = g_Ob + ((size_t)b * SS + q0) * DD + h * 64;
    float* ob1 = g_Ob + ((size_t)b * SS + q1) * DD + h * 64;
#pragma unroll
    for (int f = 0; f < 8; f++) {
        int col = 8 * f + 2 * t;
        float2 v0, v1;
        v0.x = o[f][0]; v0.y = o[f][1];
        v1.x = o[f][2]; v1.y = o[f][3];
        *(float2*)&ob0[col] = v0;
        *(float2*)&ob1[col] = v1;
    }
}

// ---------------------------------------------------------------------------
extern "C" void kernel_launch(void* const* d_in, const int* in_sizes, int n_in,
                              void* d_out, int out_size)
{
    const float* queries = (const float*)d_in[0];
    const float* keys    = (const float*)d_in[1];
    const float* values  = (const float*)d_in[2];
    // d_in[3] = attn_mask (bool, causal) — applied analytically
    const float* wq = (const float*)d_in[4];
    const float* bq = (const float*)d_in[5];
    const float* wk = (const float*)d_in[6];
    const float* bk = (const float*)d_in[7];
    const float* wv = (const float*)d_in[8];
    const float* bv = (const float*)d_in[9];
    const float* wo = (const float*)d_in[10];
    const float* bo = (const float*)d_in[11];

    float* out   = (float*)d_out;
    float* attnW = out + OUT_ELEMS;

    cudaFuncSetAttribute(proj_tc, cudaFuncAttributeMaxDynamicSharedMemorySize, PJ_SMEM);
    cudaFuncSetAttribute(attn_tc, cudaFuncAttributeMaxDynamicSharedMemorySize, ATTN_SMEM);

    // 1) convert all inputs (one launch)
    cvt_all<<<16384, 256>>>((const float4*)queries, (const float4*)keys,
                            (const float4*)values,  (const float4*)wq,
                            (const float4*)wk, (const float4*)wv, (const float4*)wo);

    // 2) Q/K/V projections in one launch (grid.z = 3)
    dim3 gg(DD / 128, MROWS / 128, 3);
    proj_tc<<<gg, 256, PJ_SMEM>>>(bq, bk, bv, nullptr, 0);

    // 3) fused attention (normalized P + O, zero-fill, no rescale pass)
    dim3 ga(BB * HH, SS / 128);
    attn_tc<<<ga, 256, ATTN_SMEM>>>(attnW);

    // 4) output projection
    cvt_ob<<<MROWS * DD / 4 / 256, 256>>>(MROWS * DD / 4);
    dim3 go(DD / 128, MROWS / 128, 1);
    proj_tc<<<go, 256, PJ_SMEM>>>(bo, nullptr, nullptr, out, 3);
}

// round 6
// speedup vs baseline: 3.1098x; 1.0165x over previous
#include <cuda_runtime.h>
#include <cuda_bf16.h>
#include <cstdint>

// Problem constants
#define BB 2
#define SS 2048
#define DD 1024
#define HH 16
#define HEADD 64
#define MROWS (BB*SS)                  // 4096
#define OUT_ELEMS ((size_t)BB*SS*DD)   // 4,194,304
#define XSZ ((size_t)MROWS*DD)         // 4M elements
#define WSZ ((size_t)DD*DD)            // 1M elements

// Scratch (device globals; no allocation allowed)
// bf16 hi/lo split inputs: X slots 0..2 (queries/keys/values; attn O reuses slot 0)
__device__ __nv_bfloat16 g_Xh[3*XSZ];
__device__ __nv_bfloat16 g_Xl[3*XSZ];
// W slots 0..3 (wq,wk,wv,wo)
__device__ __nv_bfloat16 g_Wh[4*WSZ];
__device__ __nv_bfloat16 g_Wl[4*WSZ];
// Q/K/V bf16 hi/lo splits, layout [bh][s][64] (Q pre-scaled by log2e/8)
__device__ __nv_bfloat16 g_Qh[(size_t)BB*HH*SS*HEADD];
__device__ __nv_bfloat16 g_Ql[(size_t)BB*HH*SS*HEADD];
__device__ __nv_bfloat16 g_Kh[(size_t)BB*HH*SS*HEADD];
__device__ __nv_bfloat16 g_Kl[(size_t)BB*HH*SS*HEADD];
__device__ __nv_bfloat16 g_Vh[(size_t)BB*HH*SS*HEADD];
__device__ __nv_bfloat16 g_Vl[(size_t)BB*HH*SS*HEADD];

// ---------------------------------------------------------------------------
// Helpers (plain sm_103-safe: mma.sync + ldmatrix + cp.async, sm_80 ISA)
// ---------------------------------------------------------------------------
__device__ __forceinline__ uint32_t smem_to_u32(const void* p) {
    uint32_t a;
    asm("{ .reg .u64 t; cvta.to.shared.u64 t, %1; cvt.u32.u64 %0, t; }"
        : "=r"(a) : "l"(p));
    return a;
}
__device__ __forceinline__ void ldsm4(uint32_t* r, uint32_t addr) {
    asm volatile("ldmatrix.sync.aligned.m8n8.x4.shared.b16 {%0,%1,%2,%3}, [%4];"
        : "=r"(r[0]), "=r"(r[1]), "=r"(r[2]), "=r"(r[3]) : "r"(addr));
}
__device__ __forceinline__ void ldsm4t(uint32_t* r, uint32_t addr) {
    asm volatile("ldmatrix.sync.aligned.m8n8.x4.trans.shared.b16 {%0,%1,%2,%3}, [%4];"
        : "=r"(r[0]), "=r"(r[1]), "=r"(r[2]), "=r"(r[3]) : "r"(addr));
}
__device__ __forceinline__ void mma_bf16(float* c, const uint32_t* a, const uint32_t* b) {
    asm volatile(
        "mma.sync.aligned.m16n8k16.row.col.f32.bf16.bf16.f32 "
        "{%0,%1,%2,%3}, {%4,%5,%6,%7}, {%8,%9}, {%0,%1,%2,%3};"
        : "+f"(c[0]), "+f"(c[1]), "+f"(c[2]), "+f"(c[3])
        : "r"(a[0]), "r"(a[1]), "r"(a[2]), "r"(a[3]), "r"(b[0]), "r"(b[1]));
}
__device__ __forceinline__ uint32_t cvt2bf(float lo, float hi) {
    uint32_t d;
    asm("cvt.rn.bf16x2.f32 %0, %1, %2;" : "=r"(d) : "f"(hi), "f"(lo));
    return d;
}
__device__ __forceinline__ float ex2f(float x) {
    float r; asm("ex2.approx.f32 %0, %1;" : "=f"(r) : "f"(x)); return r;
}
__device__ __forceinline__ void cpasync16(uint32_t saddr, const void* g) {
    asm volatile("cp.async.cg.shared.global [%0], [%1], 16;" :: "r"(saddr), "l"(g));
}
// streaming stores (written-once data: don't pollute L2)
__device__ __forceinline__ void stcs2(float* p, float x, float y) {
    asm volatile("st.global.cs.v2.f32 [%0], {%1,%2};" :: "l"(p), "f"(x), "f"(y) : "memory");
}
__device__ __forceinline__ void stcs4z(float* p) {
    asm volatile("st.global.cs.v4.f32 [%0], {%1,%1,%1,%1};" :: "l"(p), "f"(0.f) : "memory");
}
#define CP_COMMIT asm volatile("cp.async.commit_group;" ::: "memory")
#define CP_WAITG(n) asm volatile("cp.async.wait_group %0;" :: "n"(n) : "memory")

// ---------------------------------------------------------------------------
// Convert all GEMM inputs in ONE launch:
//  blocks [0,12288): queries/keys/values -> X slots 0/1/2
//  blocks [12288,16384): wq/wk/wv/wo     -> W slots 0/1/2/3
// ---------------------------------------------------------------------------
__global__ void cvt_all(const float4* __restrict__ q, const float4* __restrict__ k,
                        const float4* __restrict__ v,
                        const float4* __restrict__ wq, const float4* __restrict__ wk,
                        const float4* __restrict__ wv, const float4* __restrict__ wo)
{
    const int blk = blockIdx.x;
    const float4* src;
    uint2 *dh, *dl;
    size_t off;
    if (blk < 12288) {
        int slot = blk >> 12;
        off = (size_t)(blk & 4095) * 256 + threadIdx.x;
        src = (slot == 0) ? q : (slot == 1) ? k : v;
        dh = (uint2*)(g_Xh + slot * XSZ);
        dl = (uint2*)(g_Xl + slot * XSZ);
    } else {
        int b2 = blk - 12288;
        int slot = b2 >> 10;
        off = (size_t)(b2 & 1023) * 256 + threadIdx.x;
        src = (slot == 0) ? wq : (slot == 1) ? wk : (slot == 2) ? wv : wo;
        dh = (uint2*)(g_Wh + slot * WSZ);
        dl = (uint2*)(g_Wl + slot * WSZ);
    }
    float4 x = src[off];
    uint32_t H0 = cvt2bf(x.x, x.y);
    uint32_t H1 = cvt2bf(x.z, x.w);
    float h0 = __uint_as_float(H0 << 16), h1 = __uint_as_float(H0 & 0xFFFF0000u);
    float h2 = __uint_as_float(H1 << 16), h3 = __uint_as_float(H1 & 0xFFFF0000u);
    dh[off] = make_uint2(H0, H1);
    dl[off] = make_uint2(cvt2bf(x.x - h0, x.y - h1), cvt2bf(x.z - h2, x.w - h3));
}

// ---------------------------------------------------------------------------
// Projection GEMM: Y = X @ W^T + bias, 3-pass bf16 split, fp32 acc.
// CTA tile 128x128, K chunk 64, cp.async 3-stage pipeline (3 x 64KB stages).
// grid.z selects input slot; mode = base_mode + z.
// mode 0/1/2: emit split bf16 Q/K/V [bh][s][64] (mode 0 scaled by log2e/8);
// mode 3: row-major fp32 Yout.
// ---------------------------------------------------------------------------
#define PJ_AH 0
#define PJ_AL 16384
#define PJ_BH 32768
#define PJ_BL 49152
#define PJ_STAGE 65536
#define PJ_SMEM 196608

__global__ void __launch_bounds__(256, 1)
proj_tc(const float* __restrict__ bias0, const float* __restrict__ bias1,
        const float* __restrict__ bias2, float* __restrict__ Yout, int base_mode)
{
    extern __shared__ char smem[];
    const uint32_t sbase = smem_to_u32(smem);
    const int tid = threadIdx.x;
    const int wid = tid >> 5;
    const int lane = tid & 31;
    const int wm = wid & 1;
    const int wn = wid >> 1;
    const int m0 = blockIdx.y * 128;
    const int n0 = blockIdx.x * 128;
    const int z = blockIdx.z;
    const int mode = base_mode + z;
    const int wslot = (mode == 3) ? 3 : z;

    const __nv_bfloat16* Xh = g_Xh + (size_t)z * XSZ;
    const __nv_bfloat16* Xl = g_Xl + (size_t)z * XSZ;
    const __nv_bfloat16* Wh = g_Wh + (size_t)wslot * WSZ;
    const __nv_bfloat16* Wl = g_Wl + (size_t)wslot * WSZ;
    const float* bias = (mode == 3) ? bias0 : ((z == 0) ? bias0 : (z == 1) ? bias1 : bias2);

    float acc[4][4][4];
#pragma unroll
    for (int i = 0; i < 4; i++)
#pragma unroll
        for (int j = 0; j < 4; j++)
#pragma unroll
            for (int k = 0; k < 4; k++) acc[i][j][k] = 0.f;

    const int aRow = wm * 64 + (lane & 15);
    const int aSel = lane >> 4;
    const int bRow = wn * 32 + (lane & 7) + ((lane >> 4) << 3);
    const int bSel = (lane >> 3) & 1;

    auto issue = [&](int c) {
        const uint32_t sb = sbase + (c % 3) * PJ_STAGE;
        const int k0 = c * 64;
#pragma unroll
        for (int t = 0; t < 4; t++) {
            int i = tid + t * 256;
            int r = i >> 3, u = i & 7;
            int sw = r * 128 + ((u ^ (r & 7)) << 4);
            size_t gx = (size_t)(m0 + r) * DD + k0 + u * 8;
            size_t gw = (size_t)(n0 + r) * DD + k0 + u * 8;
            cpasync16(sb + PJ_AH + sw, Xh + gx);
            cpasync16(sb + PJ_AL + sw, Xl + gx);
            cpasync16(sb + PJ_BH + sw, Wh + gw);
            cpasync16(sb + PJ_BL + sw, Wl + gw);
        }
    };

    issue(0); CP_COMMIT;
    issue(1); CP_COMMIT;
    for (int c = 0; c < 16; c++) {
        if (c + 2 < 16) { issue(c + 2); CP_COMMIT; CP_WAITG(2); }
        else if (c + 1 < 16) CP_WAITG(1);
        else CP_WAITG(0);
        __syncthreads();
        const uint32_t sb = sbase + (c % 3) * PJ_STAGE;
#pragma unroll
        for (int ks = 0; ks < 4; ks++) {
            uint32_t ah[4][4], al[4][4], bh[2][4], bl[2][4];
#pragma unroll
            for (int mf = 0; mf < 4; mf++) {
                int row = aRow + mf * 16;
                uint32_t addr = sb + (uint32_t)row * 128
                              + (uint32_t)(((ks * 2 + aSel) ^ (row & 7)) << 4);
                ldsm4(ah[mf], addr);
                ldsm4(al[mf], addr + PJ_AL);
            }
#pragma unroll
            for (int p = 0; p < 2; p++) {
                int row = bRow + p * 16;
                uint32_t addr = sb + PJ_BH + (uint32_t)row * 128
                              + (uint32_t)(((ks * 2 + bSel) ^ (row & 7)) << 4);
                ldsm4(bh[p], addr);
                ldsm4(bl[p], addr + (PJ_BL - PJ_BH));
            }
#pragma unroll
            for (int mf = 0; mf < 4; mf++) {
#pragma unroll
                for (int nf = 0; nf < 4; nf++) {
                    const int p = nf >> 1, q = (nf & 1) * 2;
                    mma_bf16(acc[mf][nf], ah[mf], &bh[p][q]);
                    mma_bf16(acc[mf][nf], ah[mf], &bl[p][q]);
                    mma_bf16(acc[mf][nf], al[mf], &bh[p][q]);
                }
            }
        }
        __syncthreads();
    }

    // ---- epilogue ----
    if (mode == 3) {
#pragma unroll
        for (int nf = 0; nf < 4; nf++) {
            const int n = n0 + wn * 32 + nf * 8 + (lane & 3) * 2;
            const float bv0 = bias[n], bv1 = bias[n + 1];
#pragma unroll
            for (int mf = 0; mf < 4; mf++) {
                const int m = m0 + wm * 64 + mf * 16 + (lane >> 2);
                float2 v0, v1;
                v0.x = acc[mf][nf][0] + bv0; v0.y = acc[mf][nf][1] + bv1;
                v1.x = acc[mf][nf][2] + bv0; v1.y = acc[mf][nf][3] + bv1;
                *(float2*)&Yout[(size_t)m * DD + n] = v0;
                *(float2*)&Yout[(size_t)(m + 8) * DD + n] = v1;
            }
        }
    } else {
        __nv_bfloat16* dh = (mode == 0) ? g_Qh : (mode == 1) ? g_Kh : g_Vh;
        __nv_bfloat16* dl = (mode == 0) ? g_Ql : (mode == 1) ? g_Kl : g_Vl;
        const float qs = (mode == 0) ? 0.18033688011112042f : 1.0f;  // log2(e)/8
#pragma unroll
        for (int nf = 0; nf < 4; nf++) {
            const int n = n0 + wn * 32 + nf * 8 + (lane & 3) * 2;
            const float bv0 = bias[n], bv1 = bias[n + 1];
            const int h = n >> 6, hd = n & 63;
#pragma unroll
            for (int mf = 0; mf < 4; mf++) {
                const int m = m0 + wm * 64 + mf * 16 + (lane >> 2);
                const int b = m >> 11, s = m & 2047;
                float v0x = (acc[mf][nf][0] + bv0) * qs;
                float v0y = (acc[mf][nf][1] + bv1) * qs;
                float v1x = (acc[mf][nf][2] + bv0) * qs;
                float v1y = (acc[mf][nf][3] + bv1) * qs;
                uint32_t H0 = cvt2bf(v0x, v0y);
                uint32_t H1 = cvt2bf(v1x, v1y);
                float h0l = __uint_as_float(H0 << 16), h0h = __uint_as_float(H0 & 0xFFFF0000u);
                float h1l = __uint_as_float(H1 << 16), h1h = __uint_as_float(H1 & 0xFFFF0000u);
                uint32_t L0 = cvt2bf(v0x - h0l, v0y - h0h);
                uint32_t L1 = cvt2bf(v1x - h1l, v1y - h1h);
                size_t off = ((size_t)(b * HH + h) * SS + s) * 32 + (hd >> 1);
                ((uint32_t*)dh)[off] = H0;
                ((uint32_t*)dl)[off] = L0;
                ((uint32_t*)dh)[off + 256] = H1;   // row s+8
                ((uint32_t*)dl)[off + 256] = L1;
            }
        }
    }
}

// ---------------------------------------------------------------------------
// Two-phase HMMA attention. CTA = (bh, 128 q-rows), k-tiles of 64.
// Phase A: p = 2^(QK^T) row sums only — hi-only QK (1 pass) except qt==0
//          which uses the full 3-pass (small-row accuracy).
// Phase B: full 3-pass recompute, normalize p, write P (streaming), O += P V.
// Zero-fills the CTA's upper-triangle strip. O emitted as split bf16 (slot 0).
// K/V loads cp.async double-buffered.
// SMEM: Q 32KB | K stages 2x16KB | V stages 2x16KB = 96KB
// ---------------------------------------------------------------------------
#define AQH 0
#define AQL 16384
#define AK0 32768
#define AV0 65536
#define ATTN_SMEM 98304

__global__ void __launch_bounds__(256, 1) attn_tc(float* __restrict__ d_attn)
{
    extern __shared__ char smem[];
    const uint32_t sbase = smem_to_u32(smem);
    const int bh = blockIdx.x;
    const int qt = (int)gridDim.y - 1 - (int)blockIdx.y;   // big tiles first
    const int tid = threadIdx.x;
    const int wid = tid >> 5;
    const int lane = tid & 31;
    const int g = lane >> 2, t = lane & 3;
    const int qbase = qt * 128;
    const int nkt = 2 * qt + 2;
    const bool phaseA3 = (qt == 0);   // full 3-pass phase A for small rows

    // ---- load Q tiles (hi/lo), swizzled ----
    {
        const uint4* srcH = (const uint4*)g_Qh + ((size_t)bh * SS + qbase) * 8;
        const uint4* srcL = (const uint4*)g_Ql + ((size_t)bh * SS + qbase) * 8;
#pragma unroll
        for (int j = 0; j < 4; j++) {
            int i = tid + j * 256;
            int r = i >> 3, u = i & 7;
            int sw = r * 128 + ((u ^ (r & 7)) << 4);
            *(uint4*)(smem + AQH + sw) = srcH[r * 8 + u];
            *(uint4*)(smem + AQL + sw) = srcL[r * 8 + u];
        }
    }

    const int aRow = wid * 16 + (lane & 15);
    const int aSel = lane >> 4;
    const int bRowB = (lane & 7) + ((lane >> 4) << 3);
    const int bSel = (lane >> 3) & 1;
    const int vRowB = (lane & 7) + (((lane >> 3) & 1) << 3);
    const int vSel = lane >> 4;

    const int q0 = qbase + wid * 16 + g;
    const int q1 = q0 + 8;

    auto issueK = [&](int kt, int st, bool withLo) {
        size_t rb = ((size_t)bh * SS + kt * 64) * 8;
        uint32_t sb = sbase + AK0 + st * 16384;
#pragma unroll
        for (int j = 0; j < 2; j++) {
            int i = tid + j * 256;
            int r = i >> 3, u = i & 7;
            int sw = r * 128 + ((u ^ (r & 7)) << 4);
            cpasync16(sb + sw, (const uint4*)g_Kh + rb + r * 8 + u);
            if (withLo) cpasync16(sb + 8192 + sw, (const uint4*)g_Kl + rb + r * 8 + u);
        }
    };
    auto issueV = [&](int kt, int st) {
        size_t rb = ((size_t)bh * SS + kt * 64) * 8;
        uint32_t sb = sbase + AV0 + st * 16384;
#pragma unroll
        for (int j = 0; j < 2; j++) {
            int i = tid + j * 256;
            int r = i >> 3, u = i & 7;
            int sw = r * 128 + ((u ^ (r & 7)) << 4);
            cpasync16(sb + sw, (const uint4*)g_Vh + rb + r * 8 + u);
            cpasync16(sb + 8192 + sw, (const uint4*)g_Vl + rb + r * 8 + u);
        }
    };

    // S = Q K^T for one stage; three==true -> 3-pass split, else hi-only
    auto computeS = [&](int st, float s[8][4], bool three) {
        const uint32_t kb = sbase + AK0 + st * 16384;
#pragma unroll
        for (int f = 0; f < 8; f++)
#pragma unroll
            for (int k = 0; k < 4; k++) s[f][k] = 0.f;
#pragma unroll
        for (int ks = 0; ks < 4; ks++) {
            uint32_t ah[4], al[4];
            uint32_t addrA = sbase + AQH + (uint32_t)aRow * 128
                           + (uint32_t)((((ks << 1) + aSel) ^ (aRow & 7)) << 4);
            ldsm4(ah, addrA);
            if (three) ldsm4(al, addrA + (AQL - AQH));
#pragma unroll
            for (int p = 0; p < 4; p++) {
                int row = bRowB + p * 16;
                uint32_t addrB = kb + (uint32_t)row * 128
                               + (uint32_t)((((ks << 1) + bSel) ^ (row & 7)) << 4);
                uint32_t kh[4], kl[4];
                ldsm4(kh, addrB);
                mma_bf16(s[2 * p],     ah, &kh[0]);
                mma_bf16(s[2 * p + 1], ah, &kh[2]);
                if (three) {
                    ldsm4(kl, addrB + 8192);
                    mma_bf16(s[2 * p],     ah, &kl[0]);
                    mma_bf16(s[2 * p + 1], ah, &kl[2]);
                    mma_bf16(s[2 * p],     al, &kh[0]);
                    mma_bf16(s[2 * p + 1], al, &kh[2]);
                }
            }
        }
    };

    // ================= Phase A: row sums =================
    float rs0 = 0.f, rs1 = 0.f;
    issueK(0, 0, phaseA3); CP_COMMIT;
    for (int kt = 0; kt < nkt; kt++) {
        if (kt + 1 < nkt) { issueK(kt + 1, (kt + 1) & 1, phaseA3); CP_COMMIT; CP_WAITG(1); }
        else CP_WAITG(0);
        __syncthreads();
        float s[8][4];
        computeS(kt & 1, s, phaseA3);
        __syncthreads();   // stage reads done before next overwrite

        const bool full = (kt * 64 + 63) <= (qbase + wid * 16);
        const int kcb = kt * 64 + 2 * t;
#pragma unroll
        for (int f = 0; f < 8; f++) {
            int kc = kcb + 8 * f;
            float p0 = ex2f(s[f][0]);
            float p1 = ex2f(s[f][1]);
            float p2 = ex2f(s[f][2]);
            float p3 = ex2f(s[f][3]);
            if (!full) {
                p0 = (kc     <= q0) ? p0 : 0.f;
                p1 = (kc + 1 <= q0) ? p1 : 0.f;
                p2 = (kc     <= q1) ? p2 : 0.f;
                p3 = (kc + 1 <= q1) ? p3 : 0.f;
            }
            rs0 += p0 + p1;
            rs1 += p2 + p3;
        }
    }
    rs0 += __shfl_xor_sync(0xFFFFFFFFu, rs0, 1);
    rs0 += __shfl_xor_sync(0xFFFFFFFFu, rs0, 2);
    rs1 += __shfl_xor_sync(0xFFFFFFFFu, rs1, 1);
    rs1 += __shfl_xor_sync(0xFFFFFFFFu, rs1, 2);
    const float inv0 = 1.f / rs0, inv1 = 1.f / rs1;

    // ---- zero-fill this CTA's upper-triangle strip (streaming stores) ----
    {
        const int zstart = qbase + 128;
        for (int r = 0; r < 128 && zstart < SS; r++) {
            float* rowp = d_attn + ((size_t)bh * SS + qbase + r) * SS;
            for (int kc = zstart + tid * 4; kc < SS; kc += 1024)
                stcs4z(&rowp[kc]);
        }
    }

    // ================= Phase B: normalized P store + O accumulate =========
    float o[8][4];
#pragma unroll
    for (int f = 0; f < 8; f++)
#pragma unroll
        for (int k = 0; k < 4; k++) o[f][k] = 0.f;

    float* attn0 = d_attn + ((size_t)bh * SS + q0) * SS;
    float* attn1 = d_attn + ((size_t)bh * SS + q1) * SS;

    issueK(0, 0, true); issueV(0, 0); CP_COMMIT;
    for (int kt = 0; kt < nkt; kt++) {
        if (kt + 1 < nkt) {
            issueK(kt + 1, (kt + 1) & 1, true); issueV(kt + 1, (kt + 1) & 1);
            CP_COMMIT; CP_WAITG(1);
        } else CP_WAITG(0);
        __syncthreads();

        float s[8][4];
        computeS(kt & 1, s, true);

        const bool full = (kt * 64 + 63) <= (qbase + wid * 16);
        const int kcb = kt * 64 + 2 * t;
        uint32_t pah[4][4], pal[4][4];
#pragma unroll
        for (int f = 0; f < 8; f++) {
            int kc = kcb + 8 * f;
            float p0 = ex2f(s[f][0]) * inv0;
            float p1 = ex2f(s[f][1]) * inv0;
            float p2 = ex2f(s[f][2]) * inv1;
            float p3 = ex2f(s[f][3]) * inv1;
            if (!full) {
                p0 = (kc     <= q0) ? p0 : 0.f;
                p1 = (kc + 1 <= q0) ? p1 : 0.f;
                p2 = (kc     <= q1) ? p2 : 0.f;
                p3 = (kc + 1 <= q1) ? p3 : 0.f;
            }
            stcs2(&attn0[kc], p0, p1);
            stcs2(&attn1[kc], p2, p3);
            uint32_t H0 = cvt2bf(p0, p1);
            uint32_t H1 = cvt2bf(p2, p3);
            float h0 = __uint_as_float(H0 << 16), h1 = __uint_as_float(H0 & 0xFFFF0000u);
            float h2 = __uint_as_float(H1 << 16), h3 = __uint_as_float(H1 & 0xFFFF0000u);
            uint32_t L0 = cvt2bf(p0 - h0, p1 - h1);
            uint32_t L1 = cvt2bf(p2 - h2, p3 - h3);
            int ks = f >> 1, o2 = (f & 1) << 1;
            pah[ks][o2] = H0; pah[ks][o2 + 1] = H1;
            pal[ks][o2] = L0; pal[ks][o2 + 1] = L1;
        }

        // O += P V (3-pass split), V from this stage
        const uint32_t vb = sbase + AV0 + (kt & 1) * 16384;
#pragma unroll
        for (int ks = 0; ks < 4; ks++) {
            int row = vRowB + ks * 16;
#pragma unroll
            for (int p = 0; p < 4; p++) {
                int cu = p * 2 + vSel;
                uint32_t addrV = vb + (uint32_t)row * 128
                               + (uint32_t)((cu ^ (row & 7)) << 4);
                uint32_t vh[4], vl[4];
                ldsm4t(vh, addrV);
                ldsm4t(vl, addrV + 8192);
                mma_bf16(o[2 * p],     pah[ks], &vh[0]);
                mma_bf16(o[2 * p + 1], pah[ks], &vh[2]);
                mma_bf16(o[2 * p],     pah[ks], &vl[0]);
                mma_bf16(o[2 * p + 1], pah[ks], &vl[2]);
                mma_bf16(o[2 * p],     pal[ks], &vh[0]);
                mma_bf16(o[2 * p + 1], pal[ks], &vh[2]);
            }
        }
        __syncthreads();   // stage reads done before next overwrite
    }

    // ---- store O directly as split bf16 into X slot 0 (for out projection) ----
    const int b = bh >> 4, h = bh & 15;
    uint32_t* xh = (uint32_t*)g_Xh;
    uint32_t* xl = (uint32_t*)g_Xl;
    const size_t base0 = (((size_t)b * SS + q0) * DD + h * 64) >> 1;
    const size_t base1 = (((size_t)b * SS + q1) * DD + h * 64) >> 1;
#pragma unroll
    for (int f = 0; f < 8; f++) {
        int col = 8 * f + 2 * t;       // even
        float o0 = o[f][0], o1 = o[f][1], o2 = o[f][2], o3 = o[f][3];
        uint32_t H0 = cvt2bf(o0, o1);
        uint32_t H1 = cvt2bf(o2, o3);
        float h0 = __uint_as_float(H0 << 16), h1 = __uint_as_float(H0 & 0xFFFF0000u);
        float h2 = __uint_as_float(H1 << 16), h3 = __uint_as_float(H1 & 0xFFFF0000u);
        xh[base0 + (col >> 1)] = H0;
        xl[base0 + (col >> 1)] = cvt2bf(o0 - h0, o1 - h1);
        xh[base1 + (col >> 1)] = H1;
        xl[base1 + (col >> 1)] = cvt2bf(o2 - h2, o3 - h3);
    }
}

// ---------------------------------------------------------------------------
extern "C" void kernel_launch(void* const* d_in, const int* in_sizes, int n_in,
                              void* d_out, int out_size)
{
    const float* queries = (const float*)d_in[0];
    const float* keys    = (const float*)d_in[1];
    const float* values  = (const float*)d_in[2];
    // d_in[3] = attn_mask (bool, causal) — applied analytically
    const float* wq = (const float*)d_in[4];
    const float* bq = (const float*)d_in[5];
    const float* wk = (const float*)d_in[6];
    const float* bk = (const float*)d_in[7];
    const float* wv = (const float*)d_in[8];
    const float* bv = (const float*)d_in[9];
    const float* wo = (const float*)d_in[10];
    const float* bo = (const float*)d_in[11];

    float* out   = (float*)d_out;
    float* attnW = out + OUT_ELEMS;

    cudaFuncSetAttribute(proj_tc, cudaFuncAttributeMaxDynamicSharedMemorySize, PJ_SMEM);
    cudaFuncSetAttribute(attn_tc, cudaFuncAttributeMaxDynamicSharedMemorySize, ATTN_SMEM);

    // 1) convert all inputs (one launch)
    cvt_all<<<16384, 256>>>((const float4*)queries, (const float4*)keys,
                            (const float4*)values,  (const float4*)wq,
                            (const float4*)wk, (const float4*)wv, (const float4*)wo);

    // 2) Q/K/V projections in one launch (grid.z = 3)
    dim3 gg(DD / 128, MROWS / 128, 3);
    proj_tc<<<gg, 256, PJ_SMEM>>>(bq, bk, bv, nullptr, 0);

    // 3) fused attention (normalized P + O, zero-fill, split-bf16 O output)
    dim3 ga(BB * HH, SS / 128);
    attn_tc<<<ga, 256, ATTN_SMEM>>>(attnW);

    // 4) output projection (reads X slot 0 written by attn_tc)
    dim3 go(DD / 128, MROWS / 128, 1);
    proj_tc<<<go, 256, PJ_SMEM>>>(bo, nullptr, nullptr, out, 3);
}

// round 7
// speedup vs baseline: 3.3440x; 1.0753x over previous
#include <cuda_runtime.h>
#include <cuda_bf16.h>
#include <cstdint>

// Problem constants
#define BB 2
#define SS 2048
#define DD 1024
#define HH 16
#define HEADD 64
#define MROWS (BB*SS)                  // 4096
#define OUT_ELEMS ((size_t)BB*SS*DD)   // 4,194,304
#define XSZ ((size_t)MROWS*DD)         // 4M elements
#define WSZ ((size_t)DD*DD)            // 1M elements

// Scratch (device globals; no allocation allowed)
// bf16 hi/lo split inputs: X slots 0..2 (queries/keys/values; attn O reuses slot 0)
__device__ __nv_bfloat16 g_Xh[3*XSZ];
__device__ __nv_bfloat16 g_Xl[3*XSZ];
// W slots 0..3 (wq,wk,wv,wo)
__device__ __nv_bfloat16 g_Wh[4*WSZ];
__device__ __nv_bfloat16 g_Wl[4*WSZ];
// Q/K/V bf16 hi/lo splits, layout [bh][s][64] (Q pre-scaled by log2e/8)
__device__ __nv_bfloat16 g_Qh[(size_t)BB*HH*SS*HEADD];
__device__ __nv_bfloat16 g_Ql[(size_t)BB*HH*SS*HEADD];
__device__ __nv_bfloat16 g_Kh[(size_t)BB*HH*SS*HEADD];
__device__ __nv_bfloat16 g_Kl[(size_t)BB*HH*SS*HEADD];
__device__ __nv_bfloat16 g_Vh[(size_t)BB*HH*SS*HEADD];
__device__ __nv_bfloat16 g_Vl[(size_t)BB*HH*SS*HEADD];

// ---------------------------------------------------------------------------
// Helpers (plain sm_103-safe: mma.sync + ldmatrix + cp.async, sm_80 ISA)
// ---------------------------------------------------------------------------
__device__ __forceinline__ uint32_t smem_to_u32(const void* p) {
    uint32_t a;
    asm("{ .reg .u64 t; cvta.to.shared.u64 t, %1; cvt.u32.u64 %0, t; }"
        : "=r"(a) : "l"(p));
    return a;
}
__device__ __forceinline__ void ldsm4(uint32_t* r, uint32_t addr) {
    asm volatile("ldmatrix.sync.aligned.m8n8.x4.shared.b16 {%0,%1,%2,%3}, [%4];"
        : "=r"(r[0]), "=r"(r[1]), "=r"(r[2]), "=r"(r[3]) : "r"(addr));
}
__device__ __forceinline__ void ldsm4t(uint32_t* r, uint32_t addr) {
    asm volatile("ldmatrix.sync.aligned.m8n8.x4.trans.shared.b16 {%0,%1,%2,%3}, [%4];"
        : "=r"(r[0]), "=r"(r[1]), "=r"(r[2]), "=r"(r[3]) : "r"(addr));
}
__device__ __forceinline__ void mma_bf16(float* c, const uint32_t* a, const uint32_t* b) {
    asm volatile(
        "mma.sync.aligned.m16n8k16.row.col.f32.bf16.bf16.f32 "
        "{%0,%1,%2,%3}, {%4,%5,%6,%7}, {%8,%9}, {%0,%1,%2,%3};"
        : "+f"(c[0]), "+f"(c[1]), "+f"(c[2]), "+f"(c[3])
        : "r"(a[0]), "r"(a[1]), "r"(a[2]), "r"(a[3]), "r"(b[0]), "r"(b[1]));
}
__device__ __forceinline__ uint32_t cvt2bf(float lo, float hi) {
    uint32_t d;
    asm("cvt.rn.bf16x2.f32 %0, %1, %2;" : "=r"(d) : "f"(hi), "f"(lo));
    return d;
}
__device__ __forceinline__ float ex2f(float x) {
    float r; asm("ex2.approx.f32 %0, %1;" : "=f"(r) : "f"(x)); return r;
}
__device__ __forceinline__ void cpasync16(uint32_t saddr, const void* g) {
    asm volatile("cp.async.cg.shared.global [%0], [%1], 16;" :: "r"(saddr), "l"(g));
}
// streaming stores (written-once data: don't pollute L2)
__device__ __forceinline__ void stcs2(float* p, float x, float y) {
    asm volatile("st.global.cs.v2.f32 [%0], {%1,%2};" :: "l"(p), "f"(x), "f"(y) : "memory");
}
__device__ __forceinline__ void stcs4z(float* p) {
    asm volatile("st.global.cs.v4.f32 [%0], {%1,%1,%1,%1};" :: "l"(p), "f"(0.f) : "memory");
}
#define CP_COMMIT asm volatile("cp.async.commit_group;" ::: "memory")
#define CP_WAITG(n) asm volatile("cp.async.wait_group %0;" :: "n"(n) : "memory")

// ---------------------------------------------------------------------------
// Convert all GEMM inputs. 1024 blocks x 256 threads, 16 float4 per thread
// (MLP ~8 to hide DRAM latency).
//  blocks [0,768): queries/keys/values -> X slots 0/1/2 (256 blocks each)
//  blocks [768,1024): wq/wk/wv/wo      -> W slots 0/1/2/3 (64 blocks each)
// ---------------------------------------------------------------------------
__global__ void cvt_all(const float4* __restrict__ q, const float4* __restrict__ k,
                        const float4* __restrict__ v,
                        const float4* __restrict__ wq, const float4* __restrict__ wk,
                        const float4* __restrict__ wv, const float4* __restrict__ wo)
{
    const int blk = blockIdx.x;
    const float4* src;
    uint2 *dh, *dl;
    size_t base;
    if (blk < 768) {
        int slot = blk >> 8;
        base = (size_t)(blk & 255) * 4096;
        src = (slot == 0) ? q : (slot == 1) ? k : v;
        dh = (uint2*)(g_Xh + slot * XSZ);
        dl = (uint2*)(g_Xl + slot * XSZ);
    } else {
        int b2 = blk - 768;
        int slot = b2 >> 6;
        base = (size_t)(b2 & 63) * 4096;
        src = (slot == 0) ? wq : (slot == 1) ? wk : (slot == 2) ? wv : wo;
        dh = (uint2*)(g_Wh + slot * WSZ);
        dl = (uint2*)(g_Wl + slot * WSZ);
    }
#pragma unroll 4
    for (int j = 0; j < 16; j++) {
        size_t off = base + j * 256 + threadIdx.x;
        float4 x = src[off];
        uint32_t H0 = cvt2bf(x.x, x.y);
        uint32_t H1 = cvt2bf(x.z, x.w);
        float h0 = __uint_as_float(H0 << 16), h1 = __uint_as_float(H0 & 0xFFFF0000u);
        float h2 = __uint_as_float(H1 << 16), h3 = __uint_as_float(H1 & 0xFFFF0000u);
        dh[off] = make_uint2(H0, H1);
        dl[off] = make_uint2(cvt2bf(x.x - h0, x.y - h1), cvt2bf(x.z - h2, x.w - h3));
    }
}

// ---------------------------------------------------------------------------
// Projection GEMM: Y = X @ W^T + bias, 3-pass bf16 split, fp32 acc.
// 512 threads, CTA tile 128x256 (16 warps = 2m x 8n, warp tile 64x32).
// K chunk 64, cp.async double-buffered (2 x 96KB stages).
// grid.z selects input slot; mode = base_mode + z.
// mode 0/1/2: emit split bf16 Q/K/V [bh][s][64] (mode 0 scaled by log2e/8);
// mode 3: row-major fp32 Yout.
// ---------------------------------------------------------------------------
#define PJ_AH 0
#define PJ_AL 16384
#define PJ_BH 32768
#define PJ_BL 65536
#define PJ_STAGE 98304
#define PJ_SMEM 196608
#define PJ_THREADS 512

__global__ void __launch_bounds__(PJ_THREADS, 1)
proj_tc(const float* __restrict__ bias0, const float* __restrict__ bias1,
        const float* __restrict__ bias2, float* __restrict__ Yout, int base_mode)
{
    extern __shared__ char smem[];
    const uint32_t sbase = smem_to_u32(smem);
    const int tid = threadIdx.x;
    const int wid = tid >> 5;
    const int lane = tid & 31;
    const int wm = wid & 1;          // 0..1  (m)
    const int wn = wid >> 1;         // 0..7  (n)
    const int m0 = blockIdx.y * 128;
    const int n0 = blockIdx.x * 256;
    const int z = blockIdx.z;
    const int mode = base_mode + z;
    const int wslot = (mode == 3) ? 3 : z;

    const __nv_bfloat16* Xh = g_Xh + (size_t)z * XSZ;
    const __nv_bfloat16* Xl = g_Xl + (size_t)z * XSZ;
    const __nv_bfloat16* Wh = g_Wh + (size_t)wslot * WSZ;
    const __nv_bfloat16* Wl = g_Wl + (size_t)wslot * WSZ;
    const float* bias = (mode == 3) ? bias0 : ((z == 0) ? bias0 : (z == 1) ? bias1 : bias2);

    float acc[4][4][4];
#pragma unroll
    for (int i = 0; i < 4; i++)
#pragma unroll
        for (int j = 0; j < 4; j++)
#pragma unroll
            for (int k = 0; k < 4; k++) acc[i][j][k] = 0.f;

    const int aRow = wm * 64 + (lane & 15);
    const int aSel = lane >> 4;
    const int bRow = wn * 32 + (lane & 7) + ((lane >> 4) << 3);
    const int bSel = (lane >> 3) & 1;

    auto issue = [&](int c) {
        const uint32_t sb = sbase + (c & 1) * PJ_STAGE;
        const int k0 = c * 64;
        // A: 128 rows x 8 units, hi+lo
#pragma unroll
        for (int t = 0; t < 2; t++) {
            int i = tid + t * PJ_THREADS;      // 0..1023
            int r = i >> 3, u = i & 7;
            int sw = r * 128 + ((u ^ (r & 7)) << 4);
            size_t gx = (size_t)(m0 + r) * DD + k0 + u * 8;
            cpasync16(sb + PJ_AH + sw, Xh + gx);
            cpasync16(sb + PJ_AL + sw, Xl + gx);
        }
        // B: 256 rows x 8 units, hi+lo
#pragma unroll
        for (int t = 0; t < 4; t++) {
            int i = tid + t * PJ_THREADS;      // 0..2047
            int r = i >> 3, u = i & 7;
            int sw = r * 128 + ((u ^ (r & 7)) << 4);
            size_t gw = (size_t)(n0 + r) * DD + k0 + u * 8;
            cpasync16(sb + PJ_BH + sw, Wh + gw);
            cpasync16(sb + PJ_BL + sw, Wl + gw);
        }
    };

    issue(0); CP_COMMIT;
    for (int c = 0; c < 16; c++) {
        if (c + 1 < 16) { issue(c + 1); CP_COMMIT; CP_WAITG(1); }
        else CP_WAITG(0);
        __syncthreads();
        const uint32_t sb = sbase + (c & 1) * PJ_STAGE;
#pragma unroll
        for (int ks = 0; ks < 4; ks++) {
            // B fragments for this ks (warp's 32 columns)
            uint32_t bh[2][4], bl[2][4];
#pragma unroll
            for (int p = 0; p < 2; p++) {
                int row = bRow + p * 16;
                uint32_t addr = sb + PJ_BH + (uint32_t)row * 128
                              + (uint32_t)(((ks * 2 + bSel) ^ (row & 7)) << 4);
                ldsm4(bh[p], addr);
                ldsm4(bl[p], addr + (PJ_BL - PJ_BH));
            }
            // A fragments per mf (keeps register pressure low)
#pragma unroll
            for (int mf = 0; mf < 4; mf++) {
                int row = aRow + mf * 16;
                uint32_t addr = sb + (uint32_t)row * 128
                              + (uint32_t)(((ks * 2 + aSel) ^ (row & 7)) << 4);
                uint32_t ah[4], al[4];
                ldsm4(ah, addr);
                ldsm4(al, addr + PJ_AL);
#pragma unroll
                for (int nf = 0; nf < 4; nf++) {
                    const int p = nf >> 1, q = (nf & 1) * 2;
                    mma_bf16(acc[mf][nf], ah, &bh[p][q]);
                    mma_bf16(acc[mf][nf], ah, &bl[p][q]);
                    mma_bf16(acc[mf][nf], al, &bh[p][q]);
                }
            }
        }
        __syncthreads();
    }

    // ---- epilogue ----
    if (mode == 3) {
#pragma unroll
        for (int nf = 0; nf < 4; nf++) {
            const int n = n0 + wn * 32 + nf * 8 + (lane & 3) * 2;
            const float bv0 = bias[n], bv1 = bias[n + 1];
#pragma unroll
            for (int mf = 0; mf < 4; mf++) {
                const int m = m0 + wm * 64 + mf * 16 + (lane >> 2);
                float2 v0, v1;
                v0.x = acc[mf][nf][0] + bv0; v0.y = acc[mf][nf][1] + bv1;
                v1.x = acc[mf][nf][2] + bv0; v1.y = acc[mf][nf][3] + bv1;
                *(float2*)&Yout[(size_t)m * DD + n] = v0;
                *(float2*)&Yout[(size_t)(m + 8) * DD + n] = v1;
            }
        }
    } else {
        __nv_bfloat16* dh = (mode == 0) ? g_Qh : (mode == 1) ? g_Kh : g_Vh;
        __nv_bfloat16* dl = (mode == 0) ? g_Ql : (mode == 1) ? g_Kl : g_Vl;
        const float qs = (mode == 0) ? 0.18033688011112042f : 1.0f;  // log2(e)/8
#pragma unroll
        for (int nf = 0; nf < 4; nf++) {
            const int n = n0 + wn * 32 + nf * 8 + (lane & 3) * 2;
            const float bv0 = bias[n], bv1 = bias[n + 1];
            const int h = n >> 6, hd = n & 63;
#pragma unroll
            for (int mf = 0; mf < 4; mf++) {
                const int m = m0 + wm * 64 + mf * 16 + (lane >> 2);
                const int b = m >> 11, s = m & 2047;
                float v0x = (acc[mf][nf][0] + bv0) * qs;
                float v0y = (acc[mf][nf][1] + bv1) * qs;
                float v1x = (acc[mf][nf][2] + bv0) * qs;
                float v1y = (acc[mf][nf][3] + bv1) * qs;
                uint32_t H0 = cvt2bf(v0x, v0y);
                uint32_t H1 = cvt2bf(v1x, v1y);
                float h0l = __uint_as_float(H0 << 16), h0h = __uint_as_float(H0 & 0xFFFF0000u);
                float h1l = __uint_as_float(H1 << 16), h1h = __uint_as_float(H1 & 0xFFFF0000u);
                uint32_t L0 = cvt2bf(v0x - h0l, v0y - h0h);
                uint32_t L1 = cvt2bf(v1x - h1l, v1y - h1h);
                size_t off = ((size_t)(b * HH + h) * SS + s) * 32 + (hd >> 1);
                ((uint32_t*)dh)[off] = H0;
                ((uint32_t*)dl)[off] = L0;
                ((uint32_t*)dh)[off + 256] = H1;   // row s+8
                ((uint32_t*)dl)[off + 256] = L1;
            }
        }
    }
}

// ---------------------------------------------------------------------------
// Two-phase HMMA attention. CTA = (bh, 128 q-rows), k-tiles of 64.
// Phase A: p = 2^(QK^T) row sums only — hi-only QK (1 pass) except qt==0
//          which uses the full 3-pass (small-row accuracy).
// Phase B: full 3-pass recompute, normalize p, write P (streaming), O += P V.
// Zero-fills the CTA's upper-triangle strip. O emitted as split bf16 (slot 0).
// K/V loads cp.async double-buffered. 2 CTAs/SM (96KB smem each, <=128 regs).
// ---------------------------------------------------------------------------
#define AQH 0
#define AQL 16384
#define AK0 32768
#define AV0 65536
#define ATTN_SMEM 98304

__global__ void __launch_bounds__(256, 2) attn_tc(float* __restrict__ d_attn)
{
    extern __shared__ char smem[];
    const uint32_t sbase = smem_to_u32(smem);
    const int bh = blockIdx.x;
    const int qt = (int)gridDim.y - 1 - (int)blockIdx.y;   // big tiles first
    const int tid = threadIdx.x;
    const int wid = tid >> 5;
    const int lane = tid & 31;
    const int g = lane >> 2, t = lane & 3;
    const int qbase = qt * 128;
    const int nkt = 2 * qt + 2;
    const bool phaseA3 = (qt == 0);   // full 3-pass phase A for small rows

    // ---- load Q tiles (hi/lo), swizzled ----
    {
        const uint4* srcH = (const uint4*)g_Qh + ((size_t)bh * SS + qbase) * 8;
        const uint4* srcL = (const uint4*)g_Ql + ((size_t)bh * SS + qbase) * 8;
#pragma unroll
        for (int j = 0; j < 4; j++) {
            int i = tid + j * 256;
            int r = i >> 3, u = i & 7;
            int sw = r * 128 + ((u ^ (r & 7)) << 4);
            *(uint4*)(smem + AQH + sw) = srcH[r * 8 + u];
            *(uint4*)(smem + AQL + sw) = srcL[r * 8 + u];
        }
    }

    const int aRow = wid * 16 + (lane & 15);
    const int aSel = lane >> 4;
    const int bRowB = (lane & 7) + ((lane >> 4) << 3);
    const int bSel = (lane >> 3) & 1;
    const int vRowB = (lane & 7) + (((lane >> 3) & 1) << 3);
    const int vSel = lane >> 4;

    const int q0 = qbase + wid * 16 + g;
    const int q1 = q0 + 8;

    auto issueK = [&](int kt, int st, bool withLo) {
        size_t rb = ((size_t)bh * SS + kt * 64) * 8;
        uint32_t sb = sbase + AK0 + st * 16384;
#pragma unroll
        for (int j = 0; j < 2; j++) {
            int i = tid + j * 256;
            int r = i >> 3, u = i & 7;
            int sw = r * 128 + ((u ^ (r & 7)) << 4);
            cpasync16(sb + sw, (const uint4*)g_Kh + rb + r * 8 + u);
            if (withLo) cpasync16(sb + 8192 + sw, (const uint4*)g_Kl + rb + r * 8 + u);
        }
    };
    auto issueV = [&](int kt, int st) {
        size_t rb = ((size_t)bh * SS + kt * 64) * 8;
        uint32_t sb = sbase + AV0 + st * 16384;
#pragma unroll
        for (int j = 0; j < 2; j++) {
            int i = tid + j * 256;
            int r = i >> 3, u = i & 7;
            int sw = r * 128 + ((u ^ (r & 7)) << 4);
            cpasync16(sb + sw, (const uint4*)g_Vh + rb + r * 8 + u);
            cpasync16(sb + 8192 + sw, (const uint4*)g_Vl + rb + r * 8 + u);
        }
    };

    // S = Q K^T for one stage; three==true -> 3-pass split, else hi-only
    auto computeS = [&](int st, float s[8][4], bool three) {
        const uint32_t kb = sbase + AK0 + st * 16384;
#pragma unroll
        for (int f = 0; f < 8; f++)
#pragma unroll
            for (int k = 0; k < 4; k++) s[f][k] = 0.f;
#pragma unroll
        for (int ks = 0; ks < 4; ks++) {
            uint32_t ah[4], al[4];
            uint32_t addrA = sbase + AQH + (uint32_t)aRow * 128
                           + (uint32_t)((((ks << 1) + aSel) ^ (aRow & 7)) << 4);
            ldsm4(ah, addrA);
            if (three) ldsm4(al, addrA + (AQL - AQH));
#pragma unroll
            for (int p = 0; p < 4; p++) {
                int row = bRowB + p * 16;
                uint32_t addrB = kb + (uint32_t)row * 128
                               + (uint32_t)((((ks << 1) + bSel) ^ (row & 7)) << 4);
                uint32_t kh[4], kl[4];
                ldsm4(kh, addrB);
                mma_bf16(s[2 * p],     ah, &kh[0]);
                mma_bf16(s[2 * p + 1], ah, &kh[2]);
                if (three) {
                    ldsm4(kl, addrB + 8192);
                    mma_bf16(s[2 * p],     ah, &kl[0]);
                    mma_bf16(s[2 * p + 1], ah, &kl[2]);
                    mma_bf16(s[2 * p],     al, &kh[0]);
                    mma_bf16(s[2 * p + 1], al, &kh[2]);
                }
            }
        }
    };

    // ================= Phase A: row sums =================
    float rs0 = 0.f, rs1 = 0.f;
    issueK(0, 0, phaseA3); CP_COMMIT;
    for (int kt = 0; kt < nkt; kt++) {
        if (kt + 1 < nkt) { issueK(kt + 1, (kt + 1) & 1, phaseA3); CP_COMMIT; CP_WAITG(1); }
        else CP_WAITG(0);
        __syncthreads();
        float s[8][4];
        computeS(kt & 1, s, phaseA3);
        __syncthreads();   // stage reads done before next overwrite

        const bool full = (kt * 64 + 63) <= (qbase + wid * 16);
        const int kcb = kt * 64 + 2 * t;
#pragma unroll
        for (int f = 0; f < 8; f++) {
            int kc = kcb + 8 * f;
            float p0 = ex2f(s[f][0]);
            float p1 = ex2f(s[f][1]);
            float p2 = ex2f(s[f][2]);
            float p3 = ex2f(s[f][3]);
            if (!full) {
                p0 = (kc     <= q0) ? p0 : 0.f;
                p1 = (kc + 1 <= q0) ? p1 : 0.f;
                p2 = (kc     <= q1) ? p2 : 0.f;
                p3 = (kc + 1 <= q1) ? p3 : 0.f;
            }
            rs0 += p0 + p1;
            rs1 += p2 + p3;
        }
    }
    rs0 += __shfl_xor_sync(0xFFFFFFFFu, rs0, 1);
    rs0 += __shfl_xor_sync(0xFFFFFFFFu, rs0, 2);
    rs1 += __shfl_xor_sync(0xFFFFFFFFu, rs1, 1);
    rs1 += __shfl_xor_sync(0xFFFFFFFFu, rs1, 2);
    const float inv0 = 1.f / rs0, inv1 = 1.f / rs1;

    // ---- zero-fill this CTA's upper-triangle strip (streaming stores) ----
    {
        const int zstart = qbase + 128;
        for (int r = 0; r < 128 && zstart < SS; r++) {
            float* rowp = d_attn + ((size_t)bh * SS + qbase + r) * SS;
            for (int kc = zstart + tid * 4; kc < SS; kc += 1024)
                stcs4z(&rowp[kc]);
        }
    }

    // ================= Phase B: normalized P store + O accumulate =========
    float o[8][4];
#pragma unroll
    for (int f = 0; f < 8; f++)
#pragma unroll
        for (int k = 0; k < 4; k++) o[f][k] = 0.f;

    float* attn0 = d_attn + ((size_t)bh * SS + q0) * SS;
    float* attn1 = d_attn + ((size_t)bh * SS + q1) * SS;

    issueK(0, 0, true); issueV(0, 0); CP_COMMIT;
    for (int kt = 0; kt < nkt; kt++) {
        if (kt + 1 < nkt) {
            issueK(kt + 1, (kt + 1) & 1, true); issueV(kt + 1, (kt + 1) & 1);
            CP_COMMIT; CP_WAITG(1);
        } else CP_WAITG(0);
        __syncthreads();

        float s[8][4];
        computeS(kt & 1, s, true);

        const bool full = (kt * 64 + 63) <= (qbase + wid * 16);
        const int kcb = kt * 64 + 2 * t;
        uint32_t pah[4][4], pal[4][4];
#pragma unroll
        for (int f = 0; f < 8; f++) {
            int kc = kcb + 8 * f;
            float p0 = ex2f(s[f][0]) * inv0;
            float p1 = ex2f(s[f][1]) * inv0;
            float p2 = ex2f(s[f][2]) * inv1;
            float p3 = ex2f(s[f][3]) * inv1;
            if (!full) {
                p0 = (kc     <= q0) ? p0 : 0.f;
                p1 = (kc + 1 <= q0) ? p1 : 0.f;
                p2 = (kc     <= q1) ? p2 : 0.f;
                p3 = (kc + 1 <= q1) ? p3 : 0.f;
            }
            stcs2(&attn0[kc], p0, p1);
            stcs2(&attn1[kc], p2, p3);
            uint32_t H0 = cvt2bf(p0, p1);
            uint32_t H1 = cvt2bf(p2, p3);
            float h0 = __uint_as_float(H0 << 16), h1 = __uint_as_float(H0 & 0xFFFF0000u);
            float h2 = __uint_as_float(H1 << 16), h3 = __uint_as_float(H1 & 0xFFFF0000u);
            uint32_t L0 = cvt2bf(p0 - h0, p1 - h1);
            uint32_t L1 = cvt2bf(p2 - h2, p3 - h3);
            int ks = f >> 1, o2 = (f & 1) << 1;
            pah[ks][o2] = H0; pah[ks][o2 + 1] = H1;
            pal[ks][o2] = L0; pal[ks][o2 + 1] = L1;
        }

        // O += P V (3-pass split), V from this stage
        const uint32_t vb = sbase + AV0 + (kt & 1) * 16384;
#pragma unroll
        for (int ks = 0; ks < 4; ks++) {
            int row = vRowB + ks * 16;
#pragma unroll
            for (int p = 0; p < 4; p++) {
                int cu = p * 2 + vSel;
                uint32_t addrV = vb + (uint32_t)row * 128
                               + (uint32_t)((cu ^ (row & 7)) << 4);
                uint32_t vh[4], vl[4];
                ldsm4t(vh, addrV);
                ldsm4t(vl, addrV + 8192);
                mma_bf16(o[2 * p],     pah[ks], &vh[0]);
                mma_bf16(o[2 * p + 1], pah[ks], &vh[2]);
                mma_bf16(o[2 * p],     pah[ks], &vl[0]);
                mma_bf16(o[2 * p + 1], pah[ks], &vl[2]);
                mma_bf16(o[2 * p],     pal[ks], &vh[0]);
                mma_bf16(o[2 * p + 1], pal[ks], &vh[2]);
            }
        }
        __syncthreads();   // stage reads done before next overwrite
    }

    // ---- store O directly as split bf16 into X slot 0 (for out projection) ----
    const int b = bh >> 4, h = bh & 15;
    uint32_t* xh = (uint32_t*)g_Xh;
    uint32_t* xl = (uint32_t*)g_Xl;
    const size_t base0 = (((size_t)b * SS + q0) * DD + h * 64) >> 1;
    const size_t base1 = (((size_t)b * SS + q1) * DD + h * 64) >> 1;
#pragma unroll
    for (int f = 0; f < 8; f++) {
        int col = 8 * f + 2 * t;       // even
        float o0 = o[f][0], o1 = o[f][1], o2 = o[f][2], o3 = o[f][3];
        uint32_t H0 = cvt2bf(o0, o1);
        uint32_t H1 = cvt2bf(o2, o3);
        float h0 = __uint_as_float(H0 << 16), h1 = __uint_as_float(H0 & 0xFFFF0000u);
        float h2 = __uint_as_float(H1 << 16), h3 = __uint_as_float(H1 & 0xFFFF0000u);
        xh[base0 + (col >> 1)] = H0;
        xl[base0 + (col >> 1)] = cvt2bf(o0 - h0, o1 - h1);
        xh[base1 + (col >> 1)] = H1;
        xl[base1 + (col >> 1)] = cvt2bf(o2 - h2, o3 - h3);
    }
}

// ---------------------------------------------------------------------------
extern "C" void kernel_launch(void* const* d_in, const int* in_sizes, int n_in,
                              void* d_out, int out_size)
{
    const float* queries = (const float*)d_in[0];
    const float* keys    = (const float*)d_in[1];
    const float* values  = (const float*)d_in[2];
    // d_in[3] = attn_mask (bool, causal) — applied analytically
    const float* wq = (const float*)d_in[4];
    const float* bq = (const float*)d_in[5];
    const float* wk = (const float*)d_in[6];
    const float* bk = (const float*)d_in[7];
    const float* wv = (const float*)d_in[8];
    const float* bv = (const float*)d_in[9];
    const float* wo = (const float*)d_in[10];
    const float* bo = (const float*)d_in[11];

    float* out   = (float*)d_out;
    float* attnW = out + OUT_ELEMS;

    cudaFuncSetAttribute(proj_tc, cudaFuncAttributeMaxDynamicSharedMemorySize, PJ_SMEM);
    cudaFuncSetAttribute(attn_tc, cudaFuncAttributeMaxDynamicSharedMemorySize, ATTN_SMEM);

    // 1) convert all inputs (one launch, high-MLP)
    cvt_all<<<1024, 256>>>((const float4*)queries, (const float4*)keys,
                           (const float4*)values,  (const float4*)wq,
                           (const float4*)wk, (const float4*)wv, (const float4*)wo);

    // 2) Q/K/V projections in one launch (grid.z = 3)
    dim3 gg(DD / 256, MROWS / 128, 3);   // (4, 32, 3) = 384 CTAs
    proj_tc<<<gg, PJ_THREADS, PJ_SMEM>>>(bq, bk, bv, nullptr, 0);

    // 3) fused attention (normalized P + O, zero-fill, split-bf16 O output)
    dim3 ga(BB * HH, SS / 128);          // (32, 16) = 512 CTAs, 2/SM
    attn_tc<<<ga, 256, ATTN_SMEM>>>(attnW);

    // 4) output projection (reads X slot 0 written by attn_tc)
    dim3 go(DD / 256, MROWS / 128, 1);   // (4, 32) = 128 CTAs
    proj_tc<<<go, PJ_THREADS, PJ_SMEM>>>(bo, nullptr, nullptr, out, 3);
}